// round 1
// baseline (speedup 1.0000x reference)
#include <cuda_runtime.h>
#include <cuda_bf16.h>
#include <math.h>

// Problem constants
#define BATCH 4
#define SEQ   1024
#define DMODEL 1024
#define NHEADS 16
#define DK    64
#define MROWS (BATCH * SEQ)       // 4096
#define LN_EPS 1e-5f

// ---------------------------------------------------------------------------
// Scratch buffers (allocation-free rule: __device__ globals)
// ---------------------------------------------------------------------------
__device__ float g_buf1[MROWS * DMODEL];   // xq -> concat
__device__ float g_buf2[MROWS * DMODEL];   // q  -> x2
__device__ float g_buf3[MROWS * DMODEL];   // k  -> x3
__device__ float g_buf4[MROWS * DMODEL];   // v  -> h

// ---------------------------------------------------------------------------
// LayerNorm: one block per row, 256 threads, D=1024 (one float4 per thread)
// ---------------------------------------------------------------------------
__global__ void __launch_bounds__(256) ln_kernel(const float* __restrict__ X,
                                                 const float* __restrict__ gamma,
                                                 const float* __restrict__ beta,
                                                 float* __restrict__ Y)
{
    const int row = blockIdx.x;
    const int tid = threadIdx.x;
    const float4* x4 = reinterpret_cast<const float4*>(X + (size_t)row * DMODEL);
    float4 a = x4[tid];

    float s  = a.x + a.y + a.z + a.w;
    float ss = a.x*a.x + a.y*a.y + a.z*a.z + a.w*a.w;

    // warp reduce
    #pragma unroll
    for (int off = 16; off > 0; off >>= 1) {
        s  += __shfl_xor_sync(0xffffffff, s,  off);
        ss += __shfl_xor_sync(0xffffffff, ss, off);
    }
    __shared__ float red_s[8], red_ss[8];
    __shared__ float s_mu, s_inv;
    int wid = tid >> 5, lane = tid & 31;
    if (lane == 0) { red_s[wid] = s; red_ss[wid] = ss; }
    __syncthreads();
    if (tid == 0) {
        float ts = 0.f, tss = 0.f;
        #pragma unroll
        for (int i = 0; i < 8; i++) { ts += red_s[i]; tss += red_ss[i]; }
        float mu  = ts * (1.0f / DMODEL);
        float var = tss * (1.0f / DMODEL) - mu * mu;
        s_mu  = mu;
        s_inv = rsqrtf(var + LN_EPS);
    }
    __syncthreads();
    float mu = s_mu, inv = s_inv;

    float4 g4 = reinterpret_cast<const float4*>(gamma)[tid];
    float4 b4 = reinterpret_cast<const float4*>(beta)[tid];
    float4 o;
    o.x = (a.x - mu) * inv * g4.x + b4.x;
    o.y = (a.y - mu) * inv * g4.y + b4.y;
    o.z = (a.z - mu) * inv * g4.z + b4.z;
    o.w = (a.w - mu) * inv * g4.w + b4.w;
    reinterpret_cast<float4*>(Y + (size_t)row * DMODEL)[tid] = o;
}

// ---------------------------------------------------------------------------
// Register-tiled SGEMM:  C[M,N] = A[M,K] @ W[K,N] + bias (+relu | +resid)
// BM=BN=128, BK=16, 256 threads, 8x8 per thread.
// EPI: 0 = bias, 1 = bias+relu, 2 = bias+residual
// ---------------------------------------------------------------------------
#define GBM 128
#define GBN 128
#define GBK 16

template<int EPI>
__global__ void __launch_bounds__(256) sgemm_kernel(const float* __restrict__ A,
                                                    const float* __restrict__ W,
                                                    const float* __restrict__ bias,
                                                    const float* __restrict__ resid,
                                                    float* __restrict__ C,
                                                    int M, int N, int K)
{
    __shared__ float As[GBK][GBM];
    __shared__ float Bs[GBK][GBN];

    const int tid  = threadIdx.x;
    const int brow = blockIdx.y * GBM;
    const int bcol = blockIdx.x * GBN;
    const int ty   = tid >> 4;     // 0..15
    const int tx   = tid & 15;     // 0..15

    float acc[8][8] = {};

    for (int k0 = 0; k0 < K; k0 += GBK) {
        // Load A tile (128 x 16) -> transposed into As
        #pragma unroll
        for (int t = 0; t < 2; t++) {
            int idx = tid + t * 256;           // 0..511 float4 slots
            int r   = idx >> 2;                // row in tile
            int c4  = idx & 3;                 // float4 col
            float4 v = *reinterpret_cast<const float4*>(
                &A[(size_t)(brow + r) * K + k0 + c4 * 4]);
            As[c4*4 + 0][r] = v.x;
            As[c4*4 + 1][r] = v.y;
            As[c4*4 + 2][r] = v.z;
            As[c4*4 + 3][r] = v.w;
        }
        // Load B tile (16 x 128)
        #pragma unroll
        for (int t = 0; t < 2; t++) {
            int idx = tid + t * 256;
            int r   = idx >> 5;                // 0..15
            int c4  = idx & 31;
            *reinterpret_cast<float4*>(&Bs[r][c4*4]) =
                *reinterpret_cast<const float4*>(&W[(size_t)(k0 + r) * N + bcol + c4*4]);
        }
        __syncthreads();

        #pragma unroll
        for (int kk = 0; kk < GBK; kk++) {
            float a[8], b[8];
            #pragma unroll
            for (int i = 0; i < 8; i++) a[i] = As[kk][ty*8 + i];
            #pragma unroll
            for (int j = 0; j < 8; j++) b[j] = Bs[kk][tx*8 + j];
            #pragma unroll
            for (int i = 0; i < 8; i++)
                #pragma unroll
                for (int j = 0; j < 8; j++)
                    acc[i][j] = fmaf(a[i], b[j], acc[i][j]);
        }
        __syncthreads();
    }

    // Epilogue (vectorized, N cols are 4-aligned)
    #pragma unroll
    for (int i = 0; i < 8; i++) {
        int row = brow + ty*8 + i;
        #pragma unroll
        for (int j4 = 0; j4 < 2; j4++) {
            int col = bcol + tx*8 + j4*4;
            float4 bv = *reinterpret_cast<const float4*>(&bias[col]);
            float4 o;
            o.x = acc[i][j4*4+0] + bv.x;
            o.y = acc[i][j4*4+1] + bv.y;
            o.z = acc[i][j4*4+2] + bv.z;
            o.w = acc[i][j4*4+3] + bv.w;
            if (EPI == 1) {
                o.x = fmaxf(o.x, 0.f); o.y = fmaxf(o.y, 0.f);
                o.z = fmaxf(o.z, 0.f); o.w = fmaxf(o.w, 0.f);
            }
            if (EPI == 2) {
                float4 rv = *reinterpret_cast<const float4*>(
                    &resid[(size_t)row * N + col]);
                o.x += rv.x; o.y += rv.y; o.z += rv.z; o.w += rv.w;
            }
            *reinterpret_cast<float4*>(&C[(size_t)row * N + col]) = o;
        }
    }
}

// ---------------------------------------------------------------------------
// Fused attention (flash-style, online softmax).
// Block = (qtile of 64 rows, one (b,h)). 256 threads.
// Bq=64, Bk=32, dk=64. Q/K/V layout: [B,S,D] with head slice h*64.
// Per thread: 4 query rows (i0..i0+3), 2 key cols for scores, 4 d-cols for PV.
// ---------------------------------------------------------------------------
__global__ void __launch_bounds__(256) attn_kernel(const float* __restrict__ Q,
                                                   const float* __restrict__ Km,
                                                   const float* __restrict__ Vm,
                                                   const float* __restrict__ mask,
                                                   const unsigned char* __restrict__ kpm,
                                                   float* __restrict__ Out)
{
    __shared__ float Qs[64][65];
    __shared__ float Ks[32][65];
    __shared__ float Vs[32][64];
    __shared__ float Ps[64][33];

    const int tid = threadIdx.x;
    const int bh  = blockIdx.y;
    const int b   = bh / NHEADS;
    const int h   = bh % NHEADS;
    const int q0  = blockIdx.x * 64;

    // Load Q tile (64 x 64)
    for (int t = tid; t < 64*64; t += 256) {
        int r = t >> 6, c = t & 63;
        Qs[r][c] = Q[((size_t)(b*SEQ + q0 + r)) * DMODEL + h*DK + c];
    }

    float acc[4][4] = {};
    float mrow[4], lrow[4];
    #pragma unroll
    for (int i = 0; i < 4; i++) { mrow[i] = -1e30f; lrow[i] = 0.f; }

    const int i0  = (tid >> 4) * 4;   // query row group
    const int jj0 = (tid & 15) * 2;   // key cols for scores
    const int d0  = (tid & 15) * 4;   // d cols for PV
    const float scale = 0.125f;       // 1/sqrt(64)

    __syncthreads();

    for (int kt = 0; kt < SEQ; kt += 32) {
        // Load K,V tiles (32 x 64)
        for (int t = tid; t < 32*64; t += 256) {
            int r = t >> 6, c = t & 63;
            size_t g = ((size_t)(b*SEQ + kt + r)) * DMODEL + h*DK + c;
            Ks[r][c] = Km[g];
            Vs[r][c] = Vm[g];
        }
        __syncthreads();

        // Scores: 4 rows x 2 cols per thread
        float s[4][2] = {};
        #pragma unroll
        for (int d = 0; d < DK; d++) {
            float k0v = Ks[jj0][d];
            float k1v = Ks[jj0+1][d];
            #pragma unroll
            for (int ii = 0; ii < 4; ii++) {
                float qv = Qs[i0+ii][d];
                s[ii][0] = fmaf(qv, k0v, s[ii][0]);
                s[ii][1] = fmaf(qv, k1v, s[ii][1]);
            }
        }
        // Scale + masks
        #pragma unroll
        for (int jj = 0; jj < 2; jj++) {
            int kg = kt + jj0 + jj;
            float mk = kpm[b*SEQ + kg] ? -1e30f : 0.f;
            #pragma unroll
            for (int ii = 0; ii < 4; ii++) {
                s[ii][jj] = s[ii][jj]*scale
                          + mask[(size_t)(q0 + i0 + ii)*SEQ + kg] + mk;
            }
        }
        // Row max (local 2, then across 16 lanes sharing the row group)
        float mt[4];
        #pragma unroll
        for (int ii = 0; ii < 4; ii++) mt[ii] = fmaxf(s[ii][0], s[ii][1]);
        #pragma unroll
        for (int off = 1; off < 16; off <<= 1)
            #pragma unroll
            for (int ii = 0; ii < 4; ii++)
                mt[ii] = fmaxf(mt[ii], __shfl_xor_sync(0xffffffff, mt[ii], off));

        // Online softmax update
        float corr[4], psum[4];
        #pragma unroll
        for (int ii = 0; ii < 4; ii++) {
            float mnew = fmaxf(mrow[ii], mt[ii]);
            corr[ii] = __expf(mrow[ii] - mnew);
            mrow[ii] = mnew;
            float p0 = __expf(s[ii][0] - mnew);
            float p1 = __expf(s[ii][1] - mnew);
            s[ii][0] = p0; s[ii][1] = p1;
            psum[ii] = p0 + p1;
        }
        #pragma unroll
        for (int off = 1; off < 16; off <<= 1)
            #pragma unroll
            for (int ii = 0; ii < 4; ii++)
                psum[ii] += __shfl_xor_sync(0xffffffff, psum[ii], off);
        #pragma unroll
        for (int ii = 0; ii < 4; ii++)
            lrow[ii] = lrow[ii]*corr[ii] + psum[ii];

        // Stage P to smem, rescale accumulators
        #pragma unroll
        for (int ii = 0; ii < 4; ii++) {
            Ps[i0+ii][jj0]   = s[ii][0];
            Ps[i0+ii][jj0+1] = s[ii][1];
            #pragma unroll
            for (int dd = 0; dd < 4; dd++) acc[ii][dd] *= corr[ii];
        }
        __syncthreads();

        // PV: ctx(64x64) += P(64x32) @ V(32x64)
        #pragma unroll 8
        for (int j = 0; j < 32; j++) {
            float4 v4 = *reinterpret_cast<const float4*>(&Vs[j][d0]);
            #pragma unroll
            for (int ii = 0; ii < 4; ii++) {
                float p = Ps[i0+ii][j];
                acc[ii][0] = fmaf(p, v4.x, acc[ii][0]);
                acc[ii][1] = fmaf(p, v4.y, acc[ii][1]);
                acc[ii][2] = fmaf(p, v4.z, acc[ii][2]);
                acc[ii][3] = fmaf(p, v4.w, acc[ii][3]);
            }
        }
        __syncthreads();
    }

    // Normalize and write concat[b, q, h*64 + d]
    #pragma unroll
    for (int ii = 0; ii < 4; ii++) {
        float inv = 1.f / lrow[ii];
        int qg = q0 + i0 + ii;
        float4 o;
        o.x = acc[ii][0]*inv; o.y = acc[ii][1]*inv;
        o.z = acc[ii][2]*inv; o.w = acc[ii][3]*inv;
        *reinterpret_cast<float4*>(
            &Out[((size_t)(b*SEQ + qg)) * DMODEL + h*DK + d0]) = o;
    }
}

// ---------------------------------------------------------------------------
// Launch
// ---------------------------------------------------------------------------
extern "C" void kernel_launch(void* const* d_in, const int* in_sizes, int n_in,
                              void* d_out, int out_size)
{
    const float* x    = (const float*)d_in[0];
    const float* mask = (const float*)d_in[1];
    const unsigned char* kpm = (const unsigned char*)d_in[2];
    const float* g1   = (const float*)d_in[3];
    const float* b1n  = (const float*)d_in[4];
    const float* Wq   = (const float*)d_in[5];
    const float* bq   = (const float*)d_in[6];
    const float* Wk   = (const float*)d_in[7];
    const float* bk   = (const float*)d_in[8];
    const float* Wv   = (const float*)d_in[9];
    const float* bv   = (const float*)d_in[10];
    const float* Wo   = (const float*)d_in[11];
    const float* bo   = (const float*)d_in[12];
    const float* W1   = (const float*)d_in[13];
    const float* b1   = (const float*)d_in[14];
    const float* W2   = (const float*)d_in[15];
    const float* b2   = (const float*)d_in[16];
    float* out = (float*)d_out;

    float *B1, *B2, *B3, *B4;
    cudaGetSymbolAddress((void**)&B1, g_buf1);
    cudaGetSymbolAddress((void**)&B2, g_buf2);
    cudaGetSymbolAddress((void**)&B3, g_buf3);
    cudaGetSymbolAddress((void**)&B4, g_buf4);

    const int M = MROWS, N = DMODEL, K = DMODEL;
    dim3 gGrid(N / GBN, M / GBM);   // (8, 32)
    dim3 gBlk(256);
    dim3 aGrid(SEQ / 64, BATCH * NHEADS);  // (16, 64)

    // 1. xq = LN(x)
    ln_kernel<<<M, 256>>>(x, g1, b1n, B1);
    // 2-4. q = xq@Wq+bq ; k = x@Wk+bk ; v = x@Wv+bv
    sgemm_kernel<0><<<gGrid, gBlk>>>(B1, Wq, bq, nullptr, B2, M, N, K);
    sgemm_kernel<0><<<gGrid, gBlk>>>(x,  Wk, bk, nullptr, B3, M, N, K);
    sgemm_kernel<0><<<gGrid, gBlk>>>(x,  Wv, bv, nullptr, B4, M, N, K);
    // 5. attention -> concat (B1)
    attn_kernel<<<aGrid, 256>>>(B2, B3, B4, mask, kpm, B1);
    // 6. x2 = concat@Wo + bo + x  (B2)
    sgemm_kernel<2><<<gGrid, gBlk>>>(B1, Wo, bo, x, B2, M, N, K);
    // 7. x3 = LN(x2) (B3)
    ln_kernel<<<M, 256>>>(B2, g1, b1n, B3);
    // 8. h = relu(x3@W1 + b1) (B4)
    sgemm_kernel<1><<<gGrid, gBlk>>>(B3, W1, b1, nullptr, B4, M, N, K);
    // 9. out = x3 + h@W2 + b2
    sgemm_kernel<2><<<gGrid, gBlk>>>(B4, W2, b2, B3, out, M, N, K);
}

// round 3
// speedup vs baseline: 1.4956x; 1.4956x over previous
#include <cuda_runtime.h>
#include <cuda_bf16.h>
#include <math.h>
#include <stdint.h>

// Problem constants
#define BATCH 4
#define SEQ   1024
#define DMODEL 1024
#define NHEADS 16
#define DK    64
#define MROWS (BATCH * SEQ)       // 4096
#define LN_EPS 1e-5f

// ---------------------------------------------------------------------------
// Scratch buffers (allocation-free rule: __device__ globals)
// ---------------------------------------------------------------------------
__device__ float g_buf1[MROWS * DMODEL];   // xq -> concat
__device__ float g_buf2[MROWS * DMODEL];   // q  -> x2
__device__ float g_buf3[MROWS * DMODEL];   // k  -> x3
__device__ float g_buf4[MROWS * DMODEL];   // v  -> h
__device__ __nv_bfloat16 g_whi[DMODEL * DMODEL];   // W^T split hi  [N,K]
__device__ __nv_bfloat16 g_wlo[DMODEL * DMODEL];   // W^T split lo  [N,K]

// ---------------------------------------------------------------------------
// mma.sync m16n8k16 bf16 (sm_80+ PTX; works on plain sm_100 target)
// ---------------------------------------------------------------------------
__device__ __forceinline__ void mma16816(float* d, const uint32_t* a, const uint32_t* b)
{
    asm volatile(
        "mma.sync.aligned.m16n8k16.row.col.f32.bf16.bf16.f32 "
        "{%0,%1,%2,%3}, {%4,%5,%6,%7}, {%8,%9}, {%0,%1,%2,%3};"
        : "+f"(d[0]), "+f"(d[1]), "+f"(d[2]), "+f"(d[3])
        : "r"(a[0]), "r"(a[1]), "r"(a[2]), "r"(a[3]), "r"(b[0]), "r"(b[1]));
}

__device__ __forceinline__ void bf16_split(float a, __nv_bfloat16& hi, __nv_bfloat16& lo)
{
    hi = __float2bfloat16_rn(a);
    lo = __float2bfloat16_rn(a - __bfloat162float(hi));
}

// ---------------------------------------------------------------------------
// LayerNorm: one block per row, 256 threads, D=1024 (one float4 per thread)
// ---------------------------------------------------------------------------
__global__ void __launch_bounds__(256) ln_kernel(const float* __restrict__ X,
                                                 const float* __restrict__ gamma,
                                                 const float* __restrict__ beta,
                                                 float* __restrict__ Y)
{
    const int row = blockIdx.x;
    const int tid = threadIdx.x;
    const float4* x4 = reinterpret_cast<const float4*>(X + (size_t)row * DMODEL);
    float4 a = x4[tid];

    float s  = a.x + a.y + a.z + a.w;
    float ss = a.x*a.x + a.y*a.y + a.z*a.z + a.w*a.w;

    #pragma unroll
    for (int off = 16; off > 0; off >>= 1) {
        s  += __shfl_xor_sync(0xffffffff, s,  off);
        ss += __shfl_xor_sync(0xffffffff, ss, off);
    }
    __shared__ float red_s[8], red_ss[8];
    __shared__ float s_mu, s_inv;
    int wid = tid >> 5, lane = tid & 31;
    if (lane == 0) { red_s[wid] = s; red_ss[wid] = ss; }
    __syncthreads();
    if (tid == 0) {
        float ts = 0.f, tss = 0.f;
        #pragma unroll
        for (int i = 0; i < 8; i++) { ts += red_s[i]; tss += red_ss[i]; }
        float mu  = ts * (1.0f / DMODEL);
        float var = tss * (1.0f / DMODEL) - mu * mu;
        s_mu  = mu;
        s_inv = rsqrtf(var + LN_EPS);
    }
    __syncthreads();
    float mu = s_mu, inv = s_inv;

    float4 g4 = reinterpret_cast<const float4*>(gamma)[tid];
    float4 b4 = reinterpret_cast<const float4*>(beta)[tid];
    float4 o;
    o.x = (a.x - mu) * inv * g4.x + b4.x;
    o.y = (a.y - mu) * inv * g4.y + b4.y;
    o.z = (a.z - mu) * inv * g4.z + b4.z;
    o.w = (a.w - mu) * inv * g4.w + b4.w;
    reinterpret_cast<float4*>(Y + (size_t)row * DMODEL)[tid] = o;
}

// ---------------------------------------------------------------------------
// Transpose + split: W[K,N] fp32 row-major -> Whi/Wlo[N,K] bf16 row-major
// ---------------------------------------------------------------------------
__global__ void __launch_bounds__(256) tsplit_kernel(const float* __restrict__ W,
                                                     __nv_bfloat16* __restrict__ Bh,
                                                     __nv_bfloat16* __restrict__ Bl)
{
    __shared__ float t[32][33];
    const int n0 = blockIdx.x * 32, k0 = blockIdx.y * 32;
    const int tx = threadIdx.x, ty = threadIdx.y;
    #pragma unroll
    for (int r = 0; r < 4; r++)
        t[ty + 8*r][tx] = W[(size_t)(k0 + ty + 8*r) * DMODEL + n0 + tx];
    __syncthreads();
    #pragma unroll
    for (int r = 0; r < 4; r++) {
        int n = n0 + ty + 8*r;
        float a = t[tx][ty + 8*r];
        __nv_bfloat16 hi, lo;
        bf16_split(a, hi, lo);
        Bh[(size_t)n * DMODEL + k0 + tx] = hi;
        Bl[(size_t)n * DMODEL + k0 + tx] = lo;
    }
}

// ---------------------------------------------------------------------------
// Tensor-core split-bf16 GEMM: C[M,N] = A[M,K] @ W  (W pre-split as [N,K])
// CTA tile 128x128, 8 warps (2x4), warp tile 64x32, mma m16n8k16.
// 3 MMAs per product term: hi*hi + hi*lo + lo*hi  (fp32-accurate, ~1.5e-5)
// K chunk 32, double-buffered smem, register prefetch.
// EPI: 0 = bias, 1 = bias+relu, 2 = bias+residual
// ---------------------------------------------------------------------------
#define APAD 40                          // smem row stride in bf16 (32 + 8 pad)
#define S_AHI 0
#define S_ALO (128 * APAD)               // 5120
#define S_BHI (2 * 128 * APAD)           // 10240
#define S_BLO (3 * 128 * APAD)           // 15360
#define STAGE_ELEMS (4 * 128 * APAD)     // 20480 bf16
#define GEMM_SMEM_BYTES (2 * STAGE_ELEMS * 2)   // 81920 B

template<int EPI>
__global__ void __launch_bounds__(256) mma_gemm(const float* __restrict__ A,
                                                const __nv_bfloat16* __restrict__ Wh,
                                                const __nv_bfloat16* __restrict__ Wl,
                                                const float* __restrict__ bias,
                                                const float* __restrict__ resid,
                                                float* __restrict__ C)
{
    extern __shared__ __nv_bfloat16 sm[];
    const int tid  = threadIdx.x;
    const int wid  = tid >> 5;
    const int lane = tid & 31;
    const int gid  = lane >> 2;     // 0..7
    const int tig  = lane & 3;      // 0..3
    const int brow = blockIdx.y * 128;
    const int bcol = blockIdx.x * 128;
    const int wm   = wid >> 2;      // 0..1
    const int wn   = wid & 3;       // 0..3
    const int m0   = wm * 64;
    const int n0   = wn * 32;

    // global load mapping: thread -> (row lr, 16-col half lc)
    const int lr = tid >> 1;          // 0..127
    const int lc = (tid & 1) * 16;    // 0 | 16

    const float*         gA  = A  + (size_t)(brow + lr) * DMODEL + lc;
    const __nv_bfloat16* gWh = Wh + (size_t)(bcol + lr) * DMODEL + lc;
    const __nv_bfloat16* gWl = Wl + (size_t)(bcol + lr) * DMODEL + lc;

    float acc[4][4][4] = {};

    float4 aReg[4];
    uint4  bhReg[2], blReg[2];

    // ---- load chunk 0 ----
    #pragma unroll
    for (int j = 0; j < 4; j++)
        aReg[j] = *reinterpret_cast<const float4*>(gA + 4*j);
    bhReg[0] = *reinterpret_cast<const uint4*>(gWh);
    bhReg[1] = *reinterpret_cast<const uint4*>(gWh + 8);
    blReg[0] = *reinterpret_cast<const uint4*>(gWl);
    blReg[1] = *reinterpret_cast<const uint4*>(gWl + 8);

    // ---- store chunk 0 to stage 0 ----
    {
        __nv_bfloat16* st = sm;
        #pragma unroll
        for (int j = 0; j < 4; j++) {
            float4 v = aReg[j];
            __nv_bfloat16 h0,l0,h1,l1,h2,l2,h3,l3;
            bf16_split(v.x, h0, l0); bf16_split(v.y, h1, l1);
            bf16_split(v.z, h2, l2); bf16_split(v.w, h3, l3);
            __nv_bfloat162* ph = reinterpret_cast<__nv_bfloat162*>(st + S_AHI + lr*APAD + lc + 4*j);
            __nv_bfloat162* pl = reinterpret_cast<__nv_bfloat162*>(st + S_ALO + lr*APAD + lc + 4*j);
            ph[0] = __nv_bfloat162(h0, h1); ph[1] = __nv_bfloat162(h2, h3);
            pl[0] = __nv_bfloat162(l0, l1); pl[1] = __nv_bfloat162(l2, l3);
        }
        *reinterpret_cast<uint4*>(st + S_BHI + lr*APAD + lc)     = bhReg[0];
        *reinterpret_cast<uint4*>(st + S_BHI + lr*APAD + lc + 8) = bhReg[1];
        *reinterpret_cast<uint4*>(st + S_BLO + lr*APAD + lc)     = blReg[0];
        *reinterpret_cast<uint4*>(st + S_BLO + lr*APAD + lc + 8) = blReg[1];
    }
    __syncthreads();

    const int NCH = DMODEL / 32;   // 32 chunks
    for (int i = 0; i < NCH; i++) {
        // prefetch next chunk into registers
        if (i + 1 < NCH) {
            const int k0 = (i + 1) * 32;
            #pragma unroll
            for (int j = 0; j < 4; j++)
                aReg[j] = *reinterpret_cast<const float4*>(gA + k0 + 4*j);
            bhReg[0] = *reinterpret_cast<const uint4*>(gWh + k0);
            bhReg[1] = *reinterpret_cast<const uint4*>(gWh + k0 + 8);
            blReg[0] = *reinterpret_cast<const uint4*>(gWl + k0);
            blReg[1] = *reinterpret_cast<const uint4*>(gWl + k0 + 8);
        }

        // compute on stage i&1
        const __nv_bfloat16* st = sm + (i & 1) * STAGE_ELEMS;
        #pragma unroll
        for (int s = 0; s < 2; s++) {
            const int kb = s * 16;
            uint32_t ah[4][4], al[4][4], bh[4][2], bl[4][2];
            #pragma unroll
            for (int mf = 0; mf < 4; mf++) {
                const int r = m0 + mf*16 + gid;
                const __nv_bfloat16* pa = st + r*APAD + kb + tig*2;
                ah[mf][0] = *reinterpret_cast<const uint32_t*>(pa + S_AHI);
                ah[mf][1] = *reinterpret_cast<const uint32_t*>(pa + S_AHI + 8*APAD);
                ah[mf][2] = *reinterpret_cast<const uint32_t*>(pa + S_AHI + 8);
                ah[mf][3] = *reinterpret_cast<const uint32_t*>(pa + S_AHI + 8*APAD + 8);
                al[mf][0] = *reinterpret_cast<const uint32_t*>(pa + S_ALO);
                al[mf][1] = *reinterpret_cast<const uint32_t*>(pa + S_ALO + 8*APAD);
                al[mf][2] = *reinterpret_cast<const uint32_t*>(pa + S_ALO + 8);
                al[mf][3] = *reinterpret_cast<const uint32_t*>(pa + S_ALO + 8*APAD + 8);
            }
            #pragma unroll
            for (int nf = 0; nf < 4; nf++) {
                const int n = n0 + nf*8 + gid;
                const __nv_bfloat16* pb = st + n*APAD + kb + tig*2;
                bh[nf][0] = *reinterpret_cast<const uint32_t*>(pb + S_BHI);
                bh[nf][1] = *reinterpret_cast<const uint32_t*>(pb + S_BHI + 8);
                bl[nf][0] = *reinterpret_cast<const uint32_t*>(pb + S_BLO);
                bl[nf][1] = *reinterpret_cast<const uint32_t*>(pb + S_BLO + 8);
            }
            #pragma unroll
            for (int mf = 0; mf < 4; mf++)
                #pragma unroll
                for (int nf = 0; nf < 4; nf++) {
                    mma16816(acc[mf][nf], ah[mf], bh[nf]);
                    mma16816(acc[mf][nf], ah[mf], bl[nf]);
                    mma16816(acc[mf][nf], al[mf], bh[nf]);
                }
        }

        // store prefetched chunk to the other stage
        if (i + 1 < NCH) {
            __nv_bfloat16* so = sm + ((i + 1) & 1) * STAGE_ELEMS;
            #pragma unroll
            for (int j = 0; j < 4; j++) {
                float4 v = aReg[j];
                __nv_bfloat16 h0,l0,h1,l1,h2,l2,h3,l3;
                bf16_split(v.x, h0, l0); bf16_split(v.y, h1, l1);
                bf16_split(v.z, h2, l2); bf16_split(v.w, h3, l3);
                __nv_bfloat162* ph = reinterpret_cast<__nv_bfloat162*>(so + S_AHI + lr*APAD + lc + 4*j);
                __nv_bfloat162* pl = reinterpret_cast<__nv_bfloat162*>(so + S_ALO + lr*APAD + lc + 4*j);
                ph[0] = __nv_bfloat162(h0, h1); ph[1] = __nv_bfloat162(h2, h3);
                pl[0] = __nv_bfloat162(l0, l1); pl[1] = __nv_bfloat162(l2, l3);
            }
            *reinterpret_cast<uint4*>(so + S_BHI + lr*APAD + lc)     = bhReg[0];
            *reinterpret_cast<uint4*>(so + S_BHI + lr*APAD + lc + 8) = bhReg[1];
            *reinterpret_cast<uint4*>(so + S_BLO + lr*APAD + lc)     = blReg[0];
            *reinterpret_cast<uint4*>(so + S_BLO + lr*APAD + lc + 8) = blReg[1];
        }
        __syncthreads();
    }

    // ---- epilogue ----
    #pragma unroll
    for (int mf = 0; mf < 4; mf++) {
        #pragma unroll
        for (int nf = 0; nf < 4; nf++) {
            const int row0 = brow + m0 + mf*16 + gid;
            const int col  = bcol + n0 + nf*8 + tig*2;
            float2 bv = *reinterpret_cast<const float2*>(&bias[col]);
            float o0 = acc[mf][nf][0] + bv.x;
            float o1 = acc[mf][nf][1] + bv.y;
            float o2 = acc[mf][nf][2] + bv.x;
            float o3 = acc[mf][nf][3] + bv.y;
            if (EPI == 1) {
                o0 = fmaxf(o0, 0.f); o1 = fmaxf(o1, 0.f);
                o2 = fmaxf(o2, 0.f); o3 = fmaxf(o3, 0.f);
            }
            if (EPI == 2) {
                float2 r0 = *reinterpret_cast<const float2*>(&resid[(size_t)row0 * DMODEL + col]);
                float2 r1 = *reinterpret_cast<const float2*>(&resid[(size_t)(row0+8) * DMODEL + col]);
                o0 += r0.x; o1 += r0.y; o2 += r1.x; o3 += r1.y;
            }
            *reinterpret_cast<float2*>(&C[(size_t)row0 * DMODEL + col])      = make_float2(o0, o1);
            *reinterpret_cast<float2*>(&C[(size_t)(row0+8) * DMODEL + col])  = make_float2(o2, o3);
        }
    }
}

// ---------------------------------------------------------------------------
// Fused attention (flash-style, online softmax) — unchanged.
// ---------------------------------------------------------------------------
__global__ void __launch_bounds__(256) attn_kernel(const float* __restrict__ Q,
                                                   const float* __restrict__ Km,
                                                   const float* __restrict__ Vm,
                                                   const float* __restrict__ mask,
                                                   const unsigned char* __restrict__ kpm,
                                                   float* __restrict__ Out)
{
    __shared__ float Qs[64][65];
    __shared__ float Ks[32][65];
    __shared__ float Vs[32][64];
    __shared__ float Ps[64][33];

    const int tid = threadIdx.x;
    const int bh  = blockIdx.y;
    const int b   = bh / NHEADS;
    const int h   = bh % NHEADS;
    const int q0  = blockIdx.x * 64;

    for (int t = tid; t < 64*64; t += 256) {
        int r = t >> 6, c = t & 63;
        Qs[r][c] = Q[((size_t)(b*SEQ + q0 + r)) * DMODEL + h*DK + c];
    }

    float acc[4][4] = {};
    float mrow[4], lrow[4];
    #pragma unroll
    for (int i = 0; i < 4; i++) { mrow[i] = -1e30f; lrow[i] = 0.f; }

    const int i0  = (tid >> 4) * 4;
    const int jj0 = (tid & 15) * 2;
    const int d0  = (tid & 15) * 4;
    const float scale = 0.125f;

    __syncthreads();

    for (int kt = 0; kt < SEQ; kt += 32) {
        for (int t = tid; t < 32*64; t += 256) {
            int r = t >> 6, c = t & 63;
            size_t g = ((size_t)(b*SEQ + kt + r)) * DMODEL + h*DK + c;
            Ks[r][c] = Km[g];
            Vs[r][c] = Vm[g];
        }
        __syncthreads();

        float s[4][2] = {};
        #pragma unroll
        for (int d = 0; d < DK; d++) {
            float k0v = Ks[jj0][d];
            float k1v = Ks[jj0+1][d];
            #pragma unroll
            for (int ii = 0; ii < 4; ii++) {
                float qv = Qs[i0+ii][d];
                s[ii][0] = fmaf(qv, k0v, s[ii][0]);
                s[ii][1] = fmaf(qv, k1v, s[ii][1]);
            }
        }
        #pragma unroll
        for (int jj = 0; jj < 2; jj++) {
            int kg = kt + jj0 + jj;
            float mk = kpm[b*SEQ + kg] ? -1e30f : 0.f;
            #pragma unroll
            for (int ii = 0; ii < 4; ii++) {
                s[ii][jj] = s[ii][jj]*scale
                          + mask[(size_t)(q0 + i0 + ii)*SEQ + kg] + mk;
            }
        }
        float mt[4];
        #pragma unroll
        for (int ii = 0; ii < 4; ii++) mt[ii] = fmaxf(s[ii][0], s[ii][1]);
        #pragma unroll
        for (int off = 1; off < 16; off <<= 1)
            #pragma unroll
            for (int ii = 0; ii < 4; ii++)
                mt[ii] = fmaxf(mt[ii], __shfl_xor_sync(0xffffffff, mt[ii], off));

        float corr[4], psum[4];
        #pragma unroll
        for (int ii = 0; ii < 4; ii++) {
            float mnew = fmaxf(mrow[ii], mt[ii]);
            corr[ii] = __expf(mrow[ii] - mnew);
            mrow[ii] = mnew;
            float p0 = __expf(s[ii][0] - mnew);
            float p1 = __expf(s[ii][1] - mnew);
            s[ii][0] = p0; s[ii][1] = p1;
            psum[ii] = p0 + p1;
        }
        #pragma unroll
        for (int off = 1; off < 16; off <<= 1)
            #pragma unroll
            for (int ii = 0; ii < 4; ii++)
                psum[ii] += __shfl_xor_sync(0xffffffff, psum[ii], off);
        #pragma unroll
        for (int ii = 0; ii < 4; ii++)
            lrow[ii] = lrow[ii]*corr[ii] + psum[ii];

        #pragma unroll
        for (int ii = 0; ii < 4; ii++) {
            Ps[i0+ii][jj0]   = s[ii][0];
            Ps[i0+ii][jj0+1] = s[ii][1];
            #pragma unroll
            for (int dd = 0; dd < 4; dd++) acc[ii][dd] *= corr[ii];
        }
        __syncthreads();

        #pragma unroll 8
        for (int j = 0; j < 32; j++) {
            float4 v4 = *reinterpret_cast<const float4*>(&Vs[j][d0]);
            #pragma unroll
            for (int ii = 0; ii < 4; ii++) {
                float p = Ps[i0+ii][j];
                acc[ii][0] = fmaf(p, v4.x, acc[ii][0]);
                acc[ii][1] = fmaf(p, v4.y, acc[ii][1]);
                acc[ii][2] = fmaf(p, v4.z, acc[ii][2]);
                acc[ii][3] = fmaf(p, v4.w, acc[ii][3]);
            }
        }
        __syncthreads();
    }

    #pragma unroll
    for (int ii = 0; ii < 4; ii++) {
        float inv = 1.f / lrow[ii];
        int qg = q0 + i0 + ii;
        float4 o;
        o.x = acc[ii][0]*inv; o.y = acc[ii][1]*inv;
        o.z = acc[ii][2]*inv; o.w = acc[ii][3]*inv;
        *reinterpret_cast<float4*>(
            &Out[((size_t)(b*SEQ + qg)) * DMODEL + h*DK + d0]) = o;
    }
}

// ---------------------------------------------------------------------------
// Launch
// ---------------------------------------------------------------------------
extern "C" void kernel_launch(void* const* d_in, const int* in_sizes, int n_in,
                              void* d_out, int out_size)
{
    const float* x    = (const float*)d_in[0];
    const float* mask = (const float*)d_in[1];
    const unsigned char* kpm = (const unsigned char*)d_in[2];
    const float* g1   = (const float*)d_in[3];
    const float* b1n  = (const float*)d_in[4];
    const float* Wq   = (const float*)d_in[5];
    const float* bq   = (const float*)d_in[6];
    const float* Wk   = (const float*)d_in[7];
    const float* bk   = (const float*)d_in[8];
    const float* Wv   = (const float*)d_in[9];
    const float* bv   = (const float*)d_in[10];
    const float* Wo   = (const float*)d_in[11];
    const float* bo   = (const float*)d_in[12];
    const float* W1   = (const float*)d_in[13];
    const float* b1   = (const float*)d_in[14];
    const float* W2   = (const float*)d_in[15];
    const float* b2   = (const float*)d_in[16];
    float* out = (float*)d_out;

    float *B1, *B2, *B3, *B4;
    __nv_bfloat16 *WHI, *WLO;
    cudaGetSymbolAddress((void**)&B1, g_buf1);
    cudaGetSymbolAddress((void**)&B2, g_buf2);
    cudaGetSymbolAddress((void**)&B3, g_buf3);
    cudaGetSymbolAddress((void**)&B4, g_buf4);
    cudaGetSymbolAddress((void**)&WHI, g_whi);
    cudaGetSymbolAddress((void**)&WLO, g_wlo);

    cudaFuncSetAttribute(mma_gemm<0>, cudaFuncAttributeMaxDynamicSharedMemorySize, GEMM_SMEM_BYTES);
    cudaFuncSetAttribute(mma_gemm<1>, cudaFuncAttributeMaxDynamicSharedMemorySize, GEMM_SMEM_BYTES);
    cudaFuncSetAttribute(mma_gemm<2>, cudaFuncAttributeMaxDynamicSharedMemorySize, GEMM_SMEM_BYTES);

    const int M = MROWS;
    dim3 gGrid(DMODEL / 128, M / 128);          // (8, 32)
    dim3 tGrid(DMODEL / 32, DMODEL / 32);       // (32, 32)
    dim3 tBlk(32, 8);
    dim3 aGrid(SEQ / 64, BATCH * NHEADS);       // (16, 64)

    // 1. xq = LN(x)
    ln_kernel<<<M, 256>>>(x, g1, b1n, B1);
    // 2. q = xq@Wq+bq
    tsplit_kernel<<<tGrid, tBlk>>>(Wq, WHI, WLO);
    mma_gemm<0><<<gGrid, 256, GEMM_SMEM_BYTES>>>(B1, WHI, WLO, bq, nullptr, B2);
    // 3. k = x@Wk+bk
    tsplit_kernel<<<tGrid, tBlk>>>(Wk, WHI, WLO);
    mma_gemm<0><<<gGrid, 256, GEMM_SMEM_BYTES>>>(x, WHI, WLO, bk, nullptr, B3);
    // 4. v = x@Wv+bv
    tsplit_kernel<<<tGrid, tBlk>>>(Wv, WHI, WLO);
    mma_gemm<0><<<gGrid, 256, GEMM_SMEM_BYTES>>>(x, WHI, WLO, bv, nullptr, B4);
    // 5. attention -> concat (B1)
    attn_kernel<<<aGrid, 256>>>(B2, B3, B4, mask, kpm, B1);
    // 6. x2 = concat@Wo + bo + x  (B2)
    tsplit_kernel<<<tGrid, tBlk>>>(Wo, WHI, WLO);
    mma_gemm<2><<<gGrid, 256, GEMM_SMEM_BYTES>>>(B1, WHI, WLO, bo, x, B2);
    // 7. x3 = LN(x2) (B3)
    ln_kernel<<<M, 256>>>(B2, g1, b1n, B3);
    // 8. h = relu(x3@W1 + b1) (B4)
    tsplit_kernel<<<tGrid, tBlk>>>(W1, WHI, WLO);
    mma_gemm<1><<<gGrid, 256, GEMM_SMEM_BYTES>>>(B3, WHI, WLO, b1, nullptr, B4);
    // 9. out = x3 + h@W2 + b2
    tsplit_kernel<<<tGrid, tBlk>>>(W2, WHI, WLO);
    mma_gemm<2><<<gGrid, 256, GEMM_SMEM_BYTES>>>(B4, WHI, WLO, b2, B3, out);
}

// round 4
// speedup vs baseline: 1.6883x; 1.1288x over previous
#include <cuda_runtime.h>
#include <cuda_bf16.h>
#include <math.h>
#include <stdint.h>

// Problem constants
#define BATCH 4
#define SEQ   1024
#define DMODEL 1024
#define NHEADS 16
#define DK    64
#define MROWS (BATCH * SEQ)       // 4096
#define LN_EPS 1e-5f

// ---------------------------------------------------------------------------
// Scratch buffers (allocation-free rule: __device__ globals)
// ---------------------------------------------------------------------------
__device__ float g_buf1[MROWS * DMODEL];   // xq -> concat
__device__ float g_buf2[MROWS * DMODEL];   // q  -> x2
__device__ float g_buf3[MROWS * DMODEL];   // k  -> x3
__device__ float g_buf4[MROWS * DMODEL];   // v  -> h
__device__ __nv_bfloat16 g_whi[DMODEL * DMODEL];   // W^T split hi  [N,K]
__device__ __nv_bfloat16 g_wlo[DMODEL * DMODEL];   // W^T split lo  [N,K]

// ---------------------------------------------------------------------------
// mma.sync m16n8k16 bf16 (sm_80+ PTX; works on plain sm_100 target)
// ---------------------------------------------------------------------------
__device__ __forceinline__ void mma16816(float* d, const uint32_t* a, const uint32_t* b)
{
    asm volatile(
        "mma.sync.aligned.m16n8k16.row.col.f32.bf16.bf16.f32 "
        "{%0,%1,%2,%3}, {%4,%5,%6,%7}, {%8,%9}, {%0,%1,%2,%3};"
        : "+f"(d[0]), "+f"(d[1]), "+f"(d[2]), "+f"(d[3])
        : "r"(a[0]), "r"(a[1]), "r"(a[2]), "r"(a[3]), "r"(b[0]), "r"(b[1]));
}

__device__ __forceinline__ void bf16_split(float a, __nv_bfloat16& hi, __nv_bfloat16& lo)
{
    hi = __float2bfloat16_rn(a);
    lo = __float2bfloat16_rn(a - __bfloat162float(hi));
}

// pack two fp32 into bf16x2 (hi) and the residual bf16x2 (lo)
__device__ __forceinline__ void pack_split2(float f0, float f1, uint32_t& hi, uint32_t& lo)
{
    __nv_bfloat16 h0, l0, h1, l1;
    bf16_split(f0, h0, l0);
    bf16_split(f1, h1, l1);
    __nv_bfloat162 hv(h0, h1), lv(l0, l1);
    hi = *reinterpret_cast<uint32_t*>(&hv);
    lo = *reinterpret_cast<uint32_t*>(&lv);
}

// ---------------------------------------------------------------------------
// LayerNorm: one block per row, 256 threads, D=1024 (one float4 per thread)
// ---------------------------------------------------------------------------
__global__ void __launch_bounds__(256) ln_kernel(const float* __restrict__ X,
                                                 const float* __restrict__ gamma,
                                                 const float* __restrict__ beta,
                                                 float* __restrict__ Y)
{
    const int row = blockIdx.x;
    const int tid = threadIdx.x;
    const float4* x4 = reinterpret_cast<const float4*>(X + (size_t)row * DMODEL);
    float4 a = x4[tid];

    float s  = a.x + a.y + a.z + a.w;
    float ss = a.x*a.x + a.y*a.y + a.z*a.z + a.w*a.w;

    #pragma unroll
    for (int off = 16; off > 0; off >>= 1) {
        s  += __shfl_xor_sync(0xffffffff, s,  off);
        ss += __shfl_xor_sync(0xffffffff, ss, off);
    }
    __shared__ float red_s[8], red_ss[8];
    __shared__ float s_mu, s_inv;
    int wid = tid >> 5, lane = tid & 31;
    if (lane == 0) { red_s[wid] = s; red_ss[wid] = ss; }
    __syncthreads();
    if (tid == 0) {
        float ts = 0.f, tss = 0.f;
        #pragma unroll
        for (int i = 0; i < 8; i++) { ts += red_s[i]; tss += red_ss[i]; }
        float mu  = ts * (1.0f / DMODEL);
        float var = tss * (1.0f / DMODEL) - mu * mu;
        s_mu  = mu;
        s_inv = rsqrtf(var + LN_EPS);
    }
    __syncthreads();
    float mu = s_mu, inv = s_inv;

    float4 g4 = reinterpret_cast<const float4*>(gamma)[tid];
    float4 b4 = reinterpret_cast<const float4*>(beta)[tid];
    float4 o;
    o.x = (a.x - mu) * inv * g4.x + b4.x;
    o.y = (a.y - mu) * inv * g4.y + b4.y;
    o.z = (a.z - mu) * inv * g4.z + b4.z;
    o.w = (a.w - mu) * inv * g4.w + b4.w;
    reinterpret_cast<float4*>(Y + (size_t)row * DMODEL)[tid] = o;
}

// ---------------------------------------------------------------------------
// Transpose + split: W[K,N] fp32 row-major -> Whi/Wlo[N,K] bf16 row-major
// ---------------------------------------------------------------------------
__global__ void __launch_bounds__(256) tsplit_kernel(const float* __restrict__ W,
                                                     __nv_bfloat16* __restrict__ Bh,
                                                     __nv_bfloat16* __restrict__ Bl)
{
    __shared__ float t[32][33];
    const int n0 = blockIdx.x * 32, k0 = blockIdx.y * 32;
    const int tx = threadIdx.x, ty = threadIdx.y;
    #pragma unroll
    for (int r = 0; r < 4; r++)
        t[ty + 8*r][tx] = W[(size_t)(k0 + ty + 8*r) * DMODEL + n0 + tx];
    __syncthreads();
    #pragma unroll
    for (int r = 0; r < 4; r++) {
        int n = n0 + ty + 8*r;
        float a = t[tx][ty + 8*r];
        __nv_bfloat16 hi, lo;
        bf16_split(a, hi, lo);
        Bh[(size_t)n * DMODEL + k0 + tx] = hi;
        Bl[(size_t)n * DMODEL + k0 + tx] = lo;
    }
}

// ---------------------------------------------------------------------------
// Tensor-core split-bf16 GEMM (unchanged from R3).
// ---------------------------------------------------------------------------
#define APAD 40
#define S_AHI 0
#define S_ALO (128 * APAD)
#define S_BHI (2 * 128 * APAD)
#define S_BLO (3 * 128 * APAD)
#define STAGE_ELEMS (4 * 128 * APAD)
#define GEMM_SMEM_BYTES (2 * STAGE_ELEMS * 2)

template<int EPI>
__global__ void __launch_bounds__(256) mma_gemm(const float* __restrict__ A,
                                                const __nv_bfloat16* __restrict__ Wh,
                                                const __nv_bfloat16* __restrict__ Wl,
                                                const float* __restrict__ bias,
                                                const float* __restrict__ resid,
                                                float* __restrict__ C)
{
    extern __shared__ __nv_bfloat16 sm[];
    const int tid  = threadIdx.x;
    const int wid  = tid >> 5;
    const int lane = tid & 31;
    const int gid  = lane >> 2;
    const int tig  = lane & 3;
    const int brow = blockIdx.y * 128;
    const int bcol = blockIdx.x * 128;
    const int wm   = wid >> 2;
    const int wn   = wid & 3;
    const int m0   = wm * 64;
    const int n0   = wn * 32;

    const int lr = tid >> 1;
    const int lc = (tid & 1) * 16;

    const float*         gA  = A  + (size_t)(brow + lr) * DMODEL + lc;
    const __nv_bfloat16* gWh = Wh + (size_t)(bcol + lr) * DMODEL + lc;
    const __nv_bfloat16* gWl = Wl + (size_t)(bcol + lr) * DMODEL + lc;

    float acc[4][4][4] = {};

    float4 aReg[4];
    uint4  bhReg[2], blReg[2];

    #pragma unroll
    for (int j = 0; j < 4; j++)
        aReg[j] = *reinterpret_cast<const float4*>(gA + 4*j);
    bhReg[0] = *reinterpret_cast<const uint4*>(gWh);
    bhReg[1] = *reinterpret_cast<const uint4*>(gWh + 8);
    blReg[0] = *reinterpret_cast<const uint4*>(gWl);
    blReg[1] = *reinterpret_cast<const uint4*>(gWl + 8);

    {
        __nv_bfloat16* st = sm;
        #pragma unroll
        for (int j = 0; j < 4; j++) {
            float4 v = aReg[j];
            __nv_bfloat16 h0,l0,h1,l1,h2,l2,h3,l3;
            bf16_split(v.x, h0, l0); bf16_split(v.y, h1, l1);
            bf16_split(v.z, h2, l2); bf16_split(v.w, h3, l3);
            __nv_bfloat162* ph = reinterpret_cast<__nv_bfloat162*>(st + S_AHI + lr*APAD + lc + 4*j);
            __nv_bfloat162* pl = reinterpret_cast<__nv_bfloat162*>(st + S_ALO + lr*APAD + lc + 4*j);
            ph[0] = __nv_bfloat162(h0, h1); ph[1] = __nv_bfloat162(h2, h3);
            pl[0] = __nv_bfloat162(l0, l1); pl[1] = __nv_bfloat162(l2, l3);
        }
        *reinterpret_cast<uint4*>(st + S_BHI + lr*APAD + lc)     = bhReg[0];
        *reinterpret_cast<uint4*>(st + S_BHI + lr*APAD + lc + 8) = bhReg[1];
        *reinterpret_cast<uint4*>(st + S_BLO + lr*APAD + lc)     = blReg[0];
        *reinterpret_cast<uint4*>(st + S_BLO + lr*APAD + lc + 8) = blReg[1];
    }
    __syncthreads();

    const int NCH = DMODEL / 32;
    for (int i = 0; i < NCH; i++) {
        if (i + 1 < NCH) {
            const int k0 = (i + 1) * 32;
            #pragma unroll
            for (int j = 0; j < 4; j++)
                aReg[j] = *reinterpret_cast<const float4*>(gA + k0 + 4*j);
            bhReg[0] = *reinterpret_cast<const uint4*>(gWh + k0);
            bhReg[1] = *reinterpret_cast<const uint4*>(gWh + k0 + 8);
            blReg[0] = *reinterpret_cast<const uint4*>(gWl + k0);
            blReg[1] = *reinterpret_cast<const uint4*>(gWl + k0 + 8);
        }

        const __nv_bfloat16* st = sm + (i & 1) * STAGE_ELEMS;
        #pragma unroll
        for (int s = 0; s < 2; s++) {
            const int kb = s * 16;
            uint32_t ah[4][4], al[4][4], bh[4][2], bl[4][2];
            #pragma unroll
            for (int mf = 0; mf < 4; mf++) {
                const int r = m0 + mf*16 + gid;
                const __nv_bfloat16* pa = st + r*APAD + kb + tig*2;
                ah[mf][0] = *reinterpret_cast<const uint32_t*>(pa + S_AHI);
                ah[mf][1] = *reinterpret_cast<const uint32_t*>(pa + S_AHI + 8*APAD);
                ah[mf][2] = *reinterpret_cast<const uint32_t*>(pa + S_AHI + 8);
                ah[mf][3] = *reinterpret_cast<const uint32_t*>(pa + S_AHI + 8*APAD + 8);
                al[mf][0] = *reinterpret_cast<const uint32_t*>(pa + S_ALO);
                al[mf][1] = *reinterpret_cast<const uint32_t*>(pa + S_ALO + 8*APAD);
                al[mf][2] = *reinterpret_cast<const uint32_t*>(pa + S_ALO + 8);
                al[mf][3] = *reinterpret_cast<const uint32_t*>(pa + S_ALO + 8*APAD + 8);
            }
            #pragma unroll
            for (int nf = 0; nf < 4; nf++) {
                const int n = n0 + nf*8 + gid;
                const __nv_bfloat16* pb = st + n*APAD + kb + tig*2;
                bh[nf][0] = *reinterpret_cast<const uint32_t*>(pb + S_BHI);
                bh[nf][1] = *reinterpret_cast<const uint32_t*>(pb + S_BHI + 8);
                bl[nf][0] = *reinterpret_cast<const uint32_t*>(pb + S_BLO);
                bl[nf][1] = *reinterpret_cast<const uint32_t*>(pb + S_BLO + 8);
            }
            #pragma unroll
            for (int mf = 0; mf < 4; mf++)
                #pragma unroll
                for (int nf = 0; nf < 4; nf++) {
                    mma16816(acc[mf][nf], ah[mf], bh[nf]);
                    mma16816(acc[mf][nf], ah[mf], bl[nf]);
                    mma16816(acc[mf][nf], al[mf], bh[nf]);
                }
        }

        if (i + 1 < NCH) {
            __nv_bfloat16* so = sm + ((i + 1) & 1) * STAGE_ELEMS;
            #pragma unroll
            for (int j = 0; j < 4; j++) {
                float4 v = aReg[j];
                __nv_bfloat16 h0,l0,h1,l1,h2,l2,h3,l3;
                bf16_split(v.x, h0, l0); bf16_split(v.y, h1, l1);
                bf16_split(v.z, h2, l2); bf16_split(v.w, h3, l3);
                __nv_bfloat162* ph = reinterpret_cast<__nv_bfloat162*>(so + S_AHI + lr*APAD + lc + 4*j);
                __nv_bfloat162* pl = reinterpret_cast<__nv_bfloat162*>(so + S_ALO + lr*APAD + lc + 4*j);
                ph[0] = __nv_bfloat162(h0, h1); ph[1] = __nv_bfloat162(h2, h3);
                pl[0] = __nv_bfloat162(l0, l1); pl[1] = __nv_bfloat162(l2, l3);
            }
            *reinterpret_cast<uint4*>(so + S_BHI + lr*APAD + lc)     = bhReg[0];
            *reinterpret_cast<uint4*>(so + S_BHI + lr*APAD + lc + 8) = bhReg[1];
            *reinterpret_cast<uint4*>(so + S_BLO + lr*APAD + lc)     = blReg[0];
            *reinterpret_cast<uint4*>(so + S_BLO + lr*APAD + lc + 8) = blReg[1];
        }
        __syncthreads();
    }

    #pragma unroll
    for (int mf = 0; mf < 4; mf++) {
        #pragma unroll
        for (int nf = 0; nf < 4; nf++) {
            const int row0 = brow + m0 + mf*16 + gid;
            const int col  = bcol + n0 + nf*8 + tig*2;
            float2 bv = *reinterpret_cast<const float2*>(&bias[col]);
            float o0 = acc[mf][nf][0] + bv.x;
            float o1 = acc[mf][nf][1] + bv.y;
            float o2 = acc[mf][nf][2] + bv.x;
            float o3 = acc[mf][nf][3] + bv.y;
            if (EPI == 1) {
                o0 = fmaxf(o0, 0.f); o1 = fmaxf(o1, 0.f);
                o2 = fmaxf(o2, 0.f); o3 = fmaxf(o3, 0.f);
            }
            if (EPI == 2) {
                float2 r0 = *reinterpret_cast<const float2*>(&resid[(size_t)row0 * DMODEL + col]);
                float2 r1 = *reinterpret_cast<const float2*>(&resid[(size_t)(row0+8) * DMODEL + col]);
                o0 += r0.x; o1 += r0.y; o2 += r1.x; o3 += r1.y;
            }
            *reinterpret_cast<float2*>(&C[(size_t)row0 * DMODEL + col])      = make_float2(o0, o1);
            *reinterpret_cast<float2*>(&C[(size_t)(row0+8) * DMODEL + col])  = make_float2(o2, o3);
        }
    }
}

// ---------------------------------------------------------------------------
// Tensor-core flash attention (split-bf16 mma, online softmax).
// Q tile 128, K tile 64, 8 warps x 16 q-rows. dk = 64.
// QK^T: 3-term split MMA. PV: P split in registers (accumulator->A-fragment
// identity), V transposed+split in smem.
// smem stride 66 bf16: conflict-free fragment LDS, 2-way on V scatter.
// ---------------------------------------------------------------------------
#define ATS 66
#define AT_QHI 0
#define AT_QLO (128 * ATS)            // 8448
#define AT_KHI (2 * 128 * ATS)        // 16896
#define AT_KLO (AT_KHI + 64 * ATS)    // 21120
#define AT_VHI (AT_KLO + 64 * ATS)    // 25344
#define AT_VLO (AT_VHI + 64 * ATS)    // 29568
#define ATTN_SMEM_BYTES ((AT_VLO + 64 * ATS) * 2)   // 67584

__global__ void __launch_bounds__(256) attn_mma_kernel(const float* __restrict__ Q,
                                                       const float* __restrict__ Km,
                                                       const float* __restrict__ Vm,
                                                       const float* __restrict__ mask,
                                                       const unsigned char* __restrict__ kpm,
                                                       float* __restrict__ Out)
{
    extern __shared__ __nv_bfloat16 sma[];
    const int tid  = threadIdx.x;
    const int wid  = tid >> 5;
    const int lane = tid & 31;
    const int gid  = lane >> 2;      // 0..7
    const int tig  = lane & 3;       // 0..3
    const int bh   = blockIdx.y;
    const int b    = bh / NHEADS;
    const int h    = bh % NHEADS;
    const int q0   = blockIdx.x * 128;
    const int qw0  = wid * 16;
    const float scale = 0.125f;      // 1/sqrt(64)

    // ---- load Q tile (128 x 64), split to hi/lo ----
    for (int t = tid; t < 128 * 16; t += 256) {     // 16 float4 per row
        int r = t >> 4, c = (t & 15) * 4;
        float4 v = *reinterpret_cast<const float4*>(
            &Q[(size_t)(b*SEQ + q0 + r) * DMODEL + h*DK + c]);
        __nv_bfloat16 h0,l0,h1,l1,h2,l2,h3,l3;
        bf16_split(v.x, h0, l0); bf16_split(v.y, h1, l1);
        bf16_split(v.z, h2, l2); bf16_split(v.w, h3, l3);
        __nv_bfloat162* ph = reinterpret_cast<__nv_bfloat162*>(sma + AT_QHI + r*ATS + c);
        __nv_bfloat162* pl = reinterpret_cast<__nv_bfloat162*>(sma + AT_QLO + r*ATS + c);
        ph[0] = __nv_bfloat162(h0, h1); ph[1] = __nv_bfloat162(h2, h3);
        pl[0] = __nv_bfloat162(l0, l1); pl[1] = __nv_bfloat162(l2, l3);
    }

    float ctx[8][4] = {};
    float mrow0 = -1e30f, mrow1 = -1e30f;
    float lrow0 = 0.f,    lrow1 = 0.f;

    const int r0g = q0 + qw0 + gid;       // global query row (first half)
    const int r1g = r0g + 8;

    for (int kt = 0; kt < SEQ; kt += 64) {
        // ---- load K tile (64x64) split; V tile transposed+split ----
        for (int t = tid; t < 64 * 16; t += 256) {
            int r = t >> 4, c = (t & 15) * 4;
            size_t g = (size_t)(b*SEQ + kt + r) * DMODEL + h*DK + c;
            float4 kv = *reinterpret_cast<const float4*>(&Km[g]);
            __nv_bfloat16 h0,l0,h1,l1,h2,l2,h3,l3;
            bf16_split(kv.x, h0, l0); bf16_split(kv.y, h1, l1);
            bf16_split(kv.z, h2, l2); bf16_split(kv.w, h3, l3);
            __nv_bfloat162* ph = reinterpret_cast<__nv_bfloat162*>(sma + AT_KHI + r*ATS + c);
            __nv_bfloat162* pl = reinterpret_cast<__nv_bfloat162*>(sma + AT_KLO + r*ATS + c);
            ph[0] = __nv_bfloat162(h0, h1); ph[1] = __nv_bfloat162(h2, h3);
            pl[0] = __nv_bfloat162(l0, l1); pl[1] = __nv_bfloat162(l2, l3);

            float4 vv = *reinterpret_cast<const float4*>(&Vm[g]);
            __nv_bfloat16 vh, vl;
            bf16_split(vv.x, vh, vl);
            sma[AT_VHI + (c+0)*ATS + r] = vh; sma[AT_VLO + (c+0)*ATS + r] = vl;
            bf16_split(vv.y, vh, vl);
            sma[AT_VHI + (c+1)*ATS + r] = vh; sma[AT_VLO + (c+1)*ATS + r] = vl;
            bf16_split(vv.z, vh, vl);
            sma[AT_VHI + (c+2)*ATS + r] = vh; sma[AT_VLO + (c+2)*ATS + r] = vl;
            bf16_split(vv.w, vh, vl);
            sma[AT_VHI + (c+3)*ATS + r] = vh; sma[AT_VLO + (c+3)*ATS + r] = vl;
        }
        __syncthreads();

        // ---- S = Q K^T (split, 3 MMAs/term), fp32 accumulators ----
        float sacc[8][4] = {};
        #pragma unroll
        for (int ks = 0; ks < 4; ks++) {
            const int kb = ks * 16;
            uint32_t qh[4], ql[4];
            const __nv_bfloat16* pa = sma + (qw0 + gid)*ATS + kb + tig*2;
            qh[0] = *reinterpret_cast<const uint32_t*>(pa + AT_QHI);
            qh[1] = *reinterpret_cast<const uint32_t*>(pa + AT_QHI + 8*ATS);
            qh[2] = *reinterpret_cast<const uint32_t*>(pa + AT_QHI + 8);
            qh[3] = *reinterpret_cast<const uint32_t*>(pa + AT_QHI + 8*ATS + 8);
            ql[0] = *reinterpret_cast<const uint32_t*>(pa + AT_QLO);
            ql[1] = *reinterpret_cast<const uint32_t*>(pa + AT_QLO + 8*ATS);
            ql[2] = *reinterpret_cast<const uint32_t*>(pa + AT_QLO + 8);
            ql[3] = *reinterpret_cast<const uint32_t*>(pa + AT_QLO + 8*ATS + 8);
            #pragma unroll
            for (int nt = 0; nt < 8; nt++) {
                uint32_t kh[2], kl[2];
                const __nv_bfloat16* pb = sma + (nt*8 + gid)*ATS + kb + tig*2;
                kh[0] = *reinterpret_cast<const uint32_t*>(pb + AT_KHI);
                kh[1] = *reinterpret_cast<const uint32_t*>(pb + AT_KHI + 8);
                kl[0] = *reinterpret_cast<const uint32_t*>(pb + AT_KLO);
                kl[1] = *reinterpret_cast<const uint32_t*>(pb + AT_KLO + 8);
                mma16816(sacc[nt], qh, kh);
                mma16816(sacc[nt], qh, kl);
                mma16816(sacc[nt], ql, kh);
            }
        }

        // ---- scale + masks ----
        float mt0 = -1e30f, mt1 = -1e30f;
        #pragma unroll
        for (int nt = 0; nt < 8; nt++) {
            const int c = kt + nt*8 + tig*2;
            const float ka0 = kpm[b*SEQ + c]     ? -1e30f : 0.f;
            const float ka1 = kpm[b*SEQ + c + 1] ? -1e30f : 0.f;
            float2 m0 = *reinterpret_cast<const float2*>(&mask[(size_t)r0g * SEQ + c]);
            float2 m1 = *reinterpret_cast<const float2*>(&mask[(size_t)r1g * SEQ + c]);
            sacc[nt][0] = sacc[nt][0]*scale + m0.x + ka0;
            sacc[nt][1] = sacc[nt][1]*scale + m0.y + ka1;
            sacc[nt][2] = sacc[nt][2]*scale + m1.x + ka0;
            sacc[nt][3] = sacc[nt][3]*scale + m1.y + ka1;
            mt0 = fmaxf(mt0, fmaxf(sacc[nt][0], sacc[nt][1]));
            mt1 = fmaxf(mt1, fmaxf(sacc[nt][2], sacc[nt][3]));
        }
        mt0 = fmaxf(mt0, __shfl_xor_sync(0xffffffff, mt0, 1));
        mt0 = fmaxf(mt0, __shfl_xor_sync(0xffffffff, mt0, 2));
        mt1 = fmaxf(mt1, __shfl_xor_sync(0xffffffff, mt1, 1));
        mt1 = fmaxf(mt1, __shfl_xor_sync(0xffffffff, mt1, 2));

        const float mn0 = fmaxf(mrow0, mt0);
        const float mn1 = fmaxf(mrow1, mt1);
        const float corr0 = __expf(mrow0 - mn0);
        const float corr1 = __expf(mrow1 - mn1);
        mrow0 = mn0; mrow1 = mn1;

        float ps0 = 0.f, ps1 = 0.f;
        #pragma unroll
        for (int nt = 0; nt < 8; nt++) {
            sacc[nt][0] = __expf(sacc[nt][0] - mn0);
            sacc[nt][1] = __expf(sacc[nt][1] - mn0);
            sacc[nt][2] = __expf(sacc[nt][2] - mn1);
            sacc[nt][3] = __expf(sacc[nt][3] - mn1);
            ps0 += sacc[nt][0] + sacc[nt][1];
            ps1 += sacc[nt][2] + sacc[nt][3];
        }
        ps0 += __shfl_xor_sync(0xffffffff, ps0, 1);
        ps0 += __shfl_xor_sync(0xffffffff, ps0, 2);
        ps1 += __shfl_xor_sync(0xffffffff, ps1, 1);
        ps1 += __shfl_xor_sync(0xffffffff, ps1, 2);
        lrow0 = lrow0 * corr0 + ps0;
        lrow1 = lrow1 * corr1 + ps1;

        #pragma unroll
        for (int dt = 0; dt < 8; dt++) {
            ctx[dt][0] *= corr0; ctx[dt][1] *= corr0;
            ctx[dt][2] *= corr1; ctx[dt][3] *= corr1;
        }

        // ---- PV: pack P fragments from accumulators, 3-term split MMA ----
        #pragma unroll
        for (int ks = 0; ks < 4; ks++) {
            uint32_t ph[4], pl[4];
            pack_split2(sacc[2*ks][0],   sacc[2*ks][1],   ph[0], pl[0]);
            pack_split2(sacc[2*ks][2],   sacc[2*ks][3],   ph[1], pl[1]);
            pack_split2(sacc[2*ks+1][0], sacc[2*ks+1][1], ph[2], pl[2]);
            pack_split2(sacc[2*ks+1][2], sacc[2*ks+1][3], ph[3], pl[3]);
            #pragma unroll
            for (int dt = 0; dt < 8; dt++) {
                uint32_t vh[2], vl[2];
                const __nv_bfloat16* pb = sma + (dt*8 + gid)*ATS + ks*16 + tig*2;
                vh[0] = *reinterpret_cast<const uint32_t*>(pb + AT_VHI);
                vh[1] = *reinterpret_cast<const uint32_t*>(pb + AT_VHI + 8);
                vl[0] = *reinterpret_cast<const uint32_t*>(pb + AT_VLO);
                vl[1] = *reinterpret_cast<const uint32_t*>(pb + AT_VLO + 8);
                mma16816(ctx[dt], ph, vh);
                mma16816(ctx[dt], ph, vl);
                mma16816(ctx[dt], pl, vh);
            }
        }
        __syncthreads();
    }

    // ---- normalize, write concat[b, q, h*64 + d] ----
    const float inv0 = 1.f / lrow0;
    const float inv1 = 1.f / lrow1;
    #pragma unroll
    for (int dt = 0; dt < 8; dt++) {
        const int col = h*DK + dt*8 + tig*2;
        *reinterpret_cast<float2*>(&Out[(size_t)(b*SEQ + r0g) * DMODEL + col]) =
            make_float2(ctx[dt][0]*inv0, ctx[dt][1]*inv0);
        *reinterpret_cast<float2*>(&Out[(size_t)(b*SEQ + r1g) * DMODEL + col]) =
            make_float2(ctx[dt][2]*inv1, ctx[dt][3]*inv1);
    }
}

// ---------------------------------------------------------------------------
// Launch
// ---------------------------------------------------------------------------
extern "C" void kernel_launch(void* const* d_in, const int* in_sizes, int n_in,
                              void* d_out, int out_size)
{
    const float* x    = (const float*)d_in[0];
    const float* mask = (const float*)d_in[1];
    const unsigned char* kpm = (const unsigned char*)d_in[2];
    const float* g1   = (const float*)d_in[3];
    const float* b1n  = (const float*)d_in[4];
    const float* Wq   = (const float*)d_in[5];
    const float* bq   = (const float*)d_in[6];
    const float* Wk   = (const float*)d_in[7];
    const float* bk   = (const float*)d_in[8];
    const float* Wv   = (const float*)d_in[9];
    const float* bv   = (const float*)d_in[10];
    const float* Wo   = (const float*)d_in[11];
    const float* bo   = (const float*)d_in[12];
    const float* W1   = (const float*)d_in[13];
    const float* b1   = (const float*)d_in[14];
    const float* W2   = (const float*)d_in[15];
    const float* b2   = (const float*)d_in[16];
    float* out = (float*)d_out;

    float *B1, *B2, *B3, *B4;
    __nv_bfloat16 *WHI, *WLO;
    cudaGetSymbolAddress((void**)&B1, g_buf1);
    cudaGetSymbolAddress((void**)&B2, g_buf2);
    cudaGetSymbolAddress((void**)&B3, g_buf3);
    cudaGetSymbolAddress((void**)&B4, g_buf4);
    cudaGetSymbolAddress((void**)&WHI, g_whi);
    cudaGetSymbolAddress((void**)&WLO, g_wlo);

    cudaFuncSetAttribute(mma_gemm<0>, cudaFuncAttributeMaxDynamicSharedMemorySize, GEMM_SMEM_BYTES);
    cudaFuncSetAttribute(mma_gemm<1>, cudaFuncAttributeMaxDynamicSharedMemorySize, GEMM_SMEM_BYTES);
    cudaFuncSetAttribute(mma_gemm<2>, cudaFuncAttributeMaxDynamicSharedMemorySize, GEMM_SMEM_BYTES);
    cudaFuncSetAttribute(attn_mma_kernel, cudaFuncAttributeMaxDynamicSharedMemorySize, ATTN_SMEM_BYTES);

    const int M = MROWS;
    dim3 gGrid(DMODEL / 128, M / 128);          // (8, 32)
    dim3 tGrid(DMODEL / 32, DMODEL / 32);       // (32, 32)
    dim3 tBlk(32, 8);
    dim3 aGrid(SEQ / 128, BATCH * NHEADS);      // (8, 64)

    // 1. xq = LN(x)
    ln_kernel<<<M, 256>>>(x, g1, b1n, B1);
    // 2. q = xq@Wq+bq
    tsplit_kernel<<<tGrid, tBlk>>>(Wq, WHI, WLO);
    mma_gemm<0><<<gGrid, 256, GEMM_SMEM_BYTES>>>(B1, WHI, WLO, bq, nullptr, B2);
    // 3. k = x@Wk+bk
    tsplit_kernel<<<tGrid, tBlk>>>(Wk, WHI, WLO);
    mma_gemm<0><<<gGrid, 256, GEMM_SMEM_BYTES>>>(x, WHI, WLO, bk, nullptr, B3);
    // 4. v = x@Wv+bv
    tsplit_kernel<<<tGrid, tBlk>>>(Wv, WHI, WLO);
    mma_gemm<0><<<gGrid, 256, GEMM_SMEM_BYTES>>>(x, WHI, WLO, bv, nullptr, B4);
    // 5. attention -> concat (B1)
    attn_mma_kernel<<<aGrid, 256, ATTN_SMEM_BYTES>>>(B2, B3, B4, mask, kpm, B1);
    // 6. x2 = concat@Wo + bo + x  (B2)
    tsplit_kernel<<<tGrid, tBlk>>>(Wo, WHI, WLO);
    mma_gemm<2><<<gGrid, 256, GEMM_SMEM_BYTES>>>(B1, WHI, WLO, bo, x, B2);
    // 7. x3 = LN(x2) (B3)
    ln_kernel<<<M, 256>>>(B2, g1, b1n, B3);
    // 8. h = relu(x3@W1 + b1) (B4)
    tsplit_kernel<<<tGrid, tBlk>>>(W1, WHI, WLO);
    mma_gemm<1><<<gGrid, 256, GEMM_SMEM_BYTES>>>(B3, WHI, WLO, b1, nullptr, B4);
    // 9. out = x3 + h@W2 + b2
    tsplit_kernel<<<tGrid, tBlk>>>(W2, WHI, WLO);
    mma_gemm<2><<<gGrid, 256, GEMM_SMEM_BYTES>>>(B4, WHI, WLO, b2, B3, out);
}

// round 5
// speedup vs baseline: 1.8504x; 1.0961x over previous
#include <cuda_runtime.h>
#include <cuda_bf16.h>
#include <math.h>
#include <stdint.h>

// Problem constants
#define BATCH 4
#define SEQ   1024
#define DMODEL 1024
#define NHEADS 16
#define DK    64
#define MROWS (BATCH * SEQ)       // 4096
#define LN_EPS 1e-5f

// ---------------------------------------------------------------------------
// Scratch buffers (allocation-free rule: __device__ globals)
// ---------------------------------------------------------------------------
__device__ float g_buf1[MROWS * DMODEL];   // xq -> concat
__device__ float g_buf2[MROWS * DMODEL];   // q  -> x2
__device__ float g_buf3[MROWS * DMODEL];   // k  -> x3
__device__ float g_buf4[MROWS * DMODEL];   // v  -> h
__device__ __nv_bfloat16 g_whi[DMODEL * DMODEL];   // W^T split hi  [N,K]
__device__ __nv_bfloat16 g_wlo[DMODEL * DMODEL];   // W^T split lo  [N,K]
__device__ __nv_bfloat16 g_ahi[MROWS * DMODEL];    // activation split hi
__device__ __nv_bfloat16 g_alo[MROWS * DMODEL];    // activation split lo

// ---------------------------------------------------------------------------
// PTX helpers
// ---------------------------------------------------------------------------
__device__ __forceinline__ uint32_t smem_to_u32(const void* smem_ptr) {
    uint32_t addr;
    asm("{ .reg .u64 tmp; cvta.to.shared.u64 tmp, %1; cvt.u32.u64 %0, tmp; }"
        : "=r"(addr) : "l"(smem_ptr));
    return addr;
}

__device__ __forceinline__ void mma16816(float* d, const uint32_t* a, const uint32_t* b)
{
    asm volatile(
        "mma.sync.aligned.m16n8k16.row.col.f32.bf16.bf16.f32 "
        "{%0,%1,%2,%3}, {%4,%5,%6,%7}, {%8,%9}, {%0,%1,%2,%3};"
        : "+f"(d[0]), "+f"(d[1]), "+f"(d[2]), "+f"(d[3])
        : "r"(a[0]), "r"(a[1]), "r"(a[2]), "r"(a[3]), "r"(b[0]), "r"(b[1]));
}

__device__ __forceinline__ void ldmx4(uint32_t* r, uint32_t addr) {
    asm volatile("ldmatrix.sync.aligned.m8n8.x4.shared.b16 {%0,%1,%2,%3}, [%4];"
        : "=r"(r[0]), "=r"(r[1]), "=r"(r[2]), "=r"(r[3]) : "r"(addr));
}
__device__ __forceinline__ void ldmx2(uint32_t* r, uint32_t addr) {
    asm volatile("ldmatrix.sync.aligned.m8n8.x2.shared.b16 {%0,%1}, [%2];"
        : "=r"(r[0]), "=r"(r[1]) : "r"(addr));
}

__device__ __forceinline__ void cp16(uint32_t dst, const void* src) {
    asm volatile("cp.async.cg.shared.global [%0], [%1], 16;" :: "r"(dst), "l"(src));
}
#define CP_COMMIT() asm volatile("cp.async.commit_group;" ::: "memory")
#define CP_WAIT0()  asm volatile("cp.async.wait_group 0;" ::: "memory")

__device__ __forceinline__ void bf16_split(float a, __nv_bfloat16& hi, __nv_bfloat16& lo)
{
    hi = __float2bfloat16_rn(a);
    lo = __float2bfloat16_rn(a - __bfloat162float(hi));
}

__device__ __forceinline__ void pack_split2(float f0, float f1, uint32_t& hi, uint32_t& lo)
{
    __nv_bfloat16 h0, l0, h1, l1;
    bf16_split(f0, h0, l0);
    bf16_split(f1, h1, l1);
    __nv_bfloat162 hv(h0, h1), lv(l0, l1);
    hi = *reinterpret_cast<uint32_t*>(&hv);
    lo = *reinterpret_cast<uint32_t*>(&lv);
}

// ---------------------------------------------------------------------------
// LayerNorm
// ---------------------------------------------------------------------------
__global__ void __launch_bounds__(256) ln_kernel(const float* __restrict__ X,
                                                 const float* __restrict__ gamma,
                                                 const float* __restrict__ beta,
                                                 float* __restrict__ Y)
{
    const int row = blockIdx.x;
    const int tid = threadIdx.x;
    const float4* x4 = reinterpret_cast<const float4*>(X + (size_t)row * DMODEL);
    float4 a = x4[tid];

    float s  = a.x + a.y + a.z + a.w;
    float ss = a.x*a.x + a.y*a.y + a.z*a.z + a.w*a.w;

    #pragma unroll
    for (int off = 16; off > 0; off >>= 1) {
        s  += __shfl_xor_sync(0xffffffff, s,  off);
        ss += __shfl_xor_sync(0xffffffff, ss, off);
    }
    __shared__ float red_s[8], red_ss[8];
    __shared__ float s_mu, s_inv;
    int wid = tid >> 5, lane = tid & 31;
    if (lane == 0) { red_s[wid] = s; red_ss[wid] = ss; }
    __syncthreads();
    if (tid == 0) {
        float ts = 0.f, tss = 0.f;
        #pragma unroll
        for (int i = 0; i < 8; i++) { ts += red_s[i]; tss += red_ss[i]; }
        float mu  = ts * (1.0f / DMODEL);
        float var = tss * (1.0f / DMODEL) - mu * mu;
        s_mu  = mu;
        s_inv = rsqrtf(var + LN_EPS);
    }
    __syncthreads();
    float mu = s_mu, inv = s_inv;

    float4 g4 = reinterpret_cast<const float4*>(gamma)[tid];
    float4 b4 = reinterpret_cast<const float4*>(beta)[tid];
    float4 o;
    o.x = (a.x - mu) * inv * g4.x + b4.x;
    o.y = (a.y - mu) * inv * g4.y + b4.y;
    o.z = (a.z - mu) * inv * g4.z + b4.z;
    o.w = (a.w - mu) * inv * g4.w + b4.w;
    reinterpret_cast<float4*>(Y + (size_t)row * DMODEL)[tid] = o;
}

// ---------------------------------------------------------------------------
// Activation split: fp32 -> bf16 hi/lo (elementwise)
// ---------------------------------------------------------------------------
__global__ void __launch_bounds__(256) split_act(const float* __restrict__ X,
                                                 __nv_bfloat16* __restrict__ H,
                                                 __nv_bfloat16* __restrict__ L)
{
    const int i = (blockIdx.x * 256 + threadIdx.x) * 4;
    float4 v = *reinterpret_cast<const float4*>(X + i);
    __nv_bfloat16 h0,l0,h1,l1,h2,l2,h3,l3;
    bf16_split(v.x, h0, l0); bf16_split(v.y, h1, l1);
    bf16_split(v.z, h2, l2); bf16_split(v.w, h3, l3);
    __nv_bfloat162 hv0(h0, h1), hv1(h2, h3), lv0(l0, l1), lv1(l2, l3);
    reinterpret_cast<__nv_bfloat162*>(H + i)[0] = hv0;
    reinterpret_cast<__nv_bfloat162*>(H + i)[1] = hv1;
    reinterpret_cast<__nv_bfloat162*>(L + i)[0] = lv0;
    reinterpret_cast<__nv_bfloat162*>(L + i)[1] = lv1;
}

// ---------------------------------------------------------------------------
// Transpose + split: W[K,N] fp32 row-major -> Whi/Wlo[N,K] bf16 row-major
// ---------------------------------------------------------------------------
__global__ void __launch_bounds__(256) tsplit_kernel(const float* __restrict__ W,
                                                     __nv_bfloat16* __restrict__ Bh,
                                                     __nv_bfloat16* __restrict__ Bl)
{
    __shared__ float t[32][33];
    const int n0 = blockIdx.x * 32, k0 = blockIdx.y * 32;
    const int tx = threadIdx.x, ty = threadIdx.y;
    #pragma unroll
    for (int r = 0; r < 4; r++)
        t[ty + 8*r][tx] = W[(size_t)(k0 + ty + 8*r) * DMODEL + n0 + tx];
    __syncthreads();
    #pragma unroll
    for (int r = 0; r < 4; r++) {
        int n = n0 + ty + 8*r;
        float a = t[tx][ty + 8*r];
        __nv_bfloat16 hi, lo;
        bf16_split(a, hi, lo);
        Bh[(size_t)n * DMODEL + k0 + tx] = hi;
        Bl[(size_t)n * DMODEL + k0 + tx] = lo;
    }
}

// ---------------------------------------------------------------------------
// Tensor-core split-bf16 GEMM, cp.async 2-stage pipeline + ldmatrix.
// C[M,N] = A[M,K] @ W ; A pre-split (Ah,Al bf16 [M,K]); W pre-split ([N,K]).
// CTA tile 128x128, 8 warps (2x4), warp tile 64x32, mma m16n8k16.
// 3 MMAs per k-step: hi*hi + hi*lo + lo*hi.
// EPI: 0 = bias, 1 = bias+relu, 2 = bias+residual
// ---------------------------------------------------------------------------
#define APAD 40                          // smem row stride in bf16 (32 + 8 pad)
#define S_AHI 0
#define S_ALO (128 * APAD)
#define S_BHI (2 * 128 * APAD)
#define S_BLO (3 * 128 * APAD)
#define STAGE_ELEMS (4 * 128 * APAD)     // 20480 bf16
#define GEMM_SMEM_BYTES (2 * STAGE_ELEMS * 2)   // 81920 B
#define NCH (DMODEL / 32)                // 32 chunks

template<int EPI>
__global__ void __launch_bounds__(256) mma_gemm(const __nv_bfloat16* __restrict__ Ah,
                                                const __nv_bfloat16* __restrict__ Al,
                                                const __nv_bfloat16* __restrict__ Wh,
                                                const __nv_bfloat16* __restrict__ Wl,
                                                const float* __restrict__ bias,
                                                const float* __restrict__ resid,
                                                float* __restrict__ C)
{
    extern __shared__ __nv_bfloat16 sm[];
    const uint32_t smb = smem_to_u32(sm);
    const int tid  = threadIdx.x;
    const int wid  = tid >> 5;
    const int lane = tid & 31;
    const int gid  = lane >> 2;
    const int tig  = lane & 3;
    const int g8   = lane >> 3;     // 0..3 (ldmatrix address group)
    const int r8   = lane & 7;
    const int brow = blockIdx.y * 128;
    const int bcol = blockIdx.x * 128;
    const int m0   = (wid >> 2) * 64;
    const int n0   = (wid & 3) * 32;

    const __nv_bfloat16* gsrc[4] = {
        Ah + (size_t)brow * DMODEL,
        Al + (size_t)brow * DMODEL,
        Wh + (size_t)bcol * DMODEL,
        Wl + (size_t)bcol * DMODEL };

    // cp.async fill of one chunk into one stage: 2048 x 16B ops, 8 per thread
    auto issue = [&](int chunk, int stage) {
        const int k0 = chunk * 32;
        #pragma unroll
        for (int j = 0; j < 8; j++) {
            const int arr = j >> 1;                       // compile-time per j
            const int rem = ((j & 1) << 8) + tid;         // 0..511
            const int r   = rem >> 2;                     // 0..127
            const int c   = (rem & 3) * 8;                // 0,8,16,24 bf16
            const __nv_bfloat16* src = gsrc[arr] + (size_t)r * DMODEL + k0 + c;
            const uint32_t dst = smb +
                (uint32_t)(stage * STAGE_ELEMS + arr * (128 * APAD) + r * APAD + c) * 2;
            cp16(dst, src);
        }
        CP_COMMIT();
    };

    float acc[4][4][4] = {};

    issue(0, 0);
    for (int i = 0; i < NCH; i++) {
        CP_WAIT0();
        __syncthreads();
        if (i + 1 < NCH) issue(i + 1, (i + 1) & 1);

        const uint32_t sb = smb + (uint32_t)((i & 1) * STAGE_ELEMS) * 2;
        #pragma unroll
        for (int s = 0; s < 2; s++) {
            const int kb = s * 16;
            uint32_t ah[4][4], al[4][4];
            #pragma unroll
            for (int mf = 0; mf < 4; mf++) {
                const int row = m0 + mf*16 + ((g8 & 1) << 3) + r8;
                const int col = kb + ((g8 >> 1) << 3);
                ldmx4(ah[mf], sb + (uint32_t)(S_AHI + row*APAD + col) * 2);
                ldmx4(al[mf], sb + (uint32_t)(S_ALO + row*APAD + col) * 2);
            }
            #pragma unroll
            for (int nf = 0; nf < 4; nf++) {
                const int rowB = n0 + nf*8 + r8;
                const int colB = kb + ((g8 & 1) << 3);
                uint32_t bh[2], bl[2];
                ldmx2(bh, sb + (uint32_t)(S_BHI + rowB*APAD + colB) * 2);
                ldmx2(bl, sb + (uint32_t)(S_BLO + rowB*APAD + colB) * 2);
                #pragma unroll
                for (int mf = 0; mf < 4; mf++) {
                    mma16816(acc[mf][nf], ah[mf], bh);
                    mma16816(acc[mf][nf], ah[mf], bl);
                    mma16816(acc[mf][nf], al[mf], bh);
                }
            }
        }
        __syncthreads();
    }

    // ---- epilogue ----
    #pragma unroll
    for (int mf = 0; mf < 4; mf++) {
        #pragma unroll
        for (int nf = 0; nf < 4; nf++) {
            const int row0 = brow + m0 + mf*16 + gid;
            const int col  = bcol + n0 + nf*8 + tig*2;
            float2 bv = *reinterpret_cast<const float2*>(&bias[col]);
            float o0 = acc[mf][nf][0] + bv.x;
            float o1 = acc[mf][nf][1] + bv.y;
            float o2 = acc[mf][nf][2] + bv.x;
            float o3 = acc[mf][nf][3] + bv.y;
            if (EPI == 1) {
                o0 = fmaxf(o0, 0.f); o1 = fmaxf(o1, 0.f);
                o2 = fmaxf(o2, 0.f); o3 = fmaxf(o3, 0.f);
            }
            if (EPI == 2) {
                float2 r0 = *reinterpret_cast<const float2*>(&resid[(size_t)row0 * DMODEL + col]);
                float2 r1 = *reinterpret_cast<const float2*>(&resid[(size_t)(row0+8) * DMODEL + col]);
                o0 += r0.x; o1 += r0.y; o2 += r1.x; o3 += r1.y;
            }
            *reinterpret_cast<float2*>(&C[(size_t)row0 * DMODEL + col])      = make_float2(o0, o1);
            *reinterpret_cast<float2*>(&C[(size_t)(row0+8) * DMODEL + col])  = make_float2(o2, o3);
        }
    }
}

// ---------------------------------------------------------------------------
// Tensor-core flash attention (split-bf16 mma, online softmax). (R4, unchanged)
// ---------------------------------------------------------------------------
#define ATS 66
#define AT_QHI 0
#define AT_QLO (128 * ATS)
#define AT_KHI (2 * 128 * ATS)
#define AT_KLO (AT_KHI + 64 * ATS)
#define AT_VHI (AT_KLO + 64 * ATS)
#define AT_VLO (AT_VHI + 64 * ATS)
#define ATTN_SMEM_BYTES ((AT_VLO + 64 * ATS) * 2)

__global__ void __launch_bounds__(256) attn_mma_kernel(const float* __restrict__ Q,
                                                       const float* __restrict__ Km,
                                                       const float* __restrict__ Vm,
                                                       const float* __restrict__ mask,
                                                       const unsigned char* __restrict__ kpm,
                                                       float* __restrict__ Out)
{
    extern __shared__ __nv_bfloat16 sma[];
    const int tid  = threadIdx.x;
    const int wid  = tid >> 5;
    const int lane = tid & 31;
    const int gid  = lane >> 2;
    const int tig  = lane & 3;
    const int bh   = blockIdx.y;
    const int b    = bh / NHEADS;
    const int h    = bh % NHEADS;
    const int q0   = blockIdx.x * 128;
    const int qw0  = wid * 16;
    const float scale = 0.125f;

    for (int t = tid; t < 128 * 16; t += 256) {
        int r = t >> 4, c = (t & 15) * 4;
        float4 v = *reinterpret_cast<const float4*>(
            &Q[(size_t)(b*SEQ + q0 + r) * DMODEL + h*DK + c]);
        __nv_bfloat16 h0,l0,h1,l1,h2,l2,h3,l3;
        bf16_split(v.x, h0, l0); bf16_split(v.y, h1, l1);
        bf16_split(v.z, h2, l2); bf16_split(v.w, h3, l3);
        __nv_bfloat162* ph = reinterpret_cast<__nv_bfloat162*>(sma + AT_QHI + r*ATS + c);
        __nv_bfloat162* pl = reinterpret_cast<__nv_bfloat162*>(sma + AT_QLO + r*ATS + c);
        ph[0] = __nv_bfloat162(h0, h1); ph[1] = __nv_bfloat162(h2, h3);
        pl[0] = __nv_bfloat162(l0, l1); pl[1] = __nv_bfloat162(l2, l3);
    }

    float ctx[8][4] = {};
    float mrow0 = -1e30f, mrow1 = -1e30f;
    float lrow0 = 0.f,    lrow1 = 0.f;

    const int r0g = q0 + qw0 + gid;
    const int r1g = r0g + 8;

    for (int kt = 0; kt < SEQ; kt += 64) {
        for (int t = tid; t < 64 * 16; t += 256) {
            int r = t >> 4, c = (t & 15) * 4;
            size_t g = (size_t)(b*SEQ + kt + r) * DMODEL + h*DK + c;
            float4 kv = *reinterpret_cast<const float4*>(&Km[g]);
            __nv_bfloat16 h0,l0,h1,l1,h2,l2,h3,l3;
            bf16_split(kv.x, h0, l0); bf16_split(kv.y, h1, l1);
            bf16_split(kv.z, h2, l2); bf16_split(kv.w, h3, l3);
            __nv_bfloat162* ph = reinterpret_cast<__nv_bfloat162*>(sma + AT_KHI + r*ATS + c);
            __nv_bfloat162* pl = reinterpret_cast<__nv_bfloat162*>(sma + AT_KLO + r*ATS + c);
            ph[0] = __nv_bfloat162(h0, h1); ph[1] = __nv_bfloat162(h2, h3);
            pl[0] = __nv_bfloat162(l0, l1); pl[1] = __nv_bfloat162(l2, l3);

            float4 vv = *reinterpret_cast<const float4*>(&Vm[g]);
            __nv_bfloat16 vh, vl;
            bf16_split(vv.x, vh, vl);
            sma[AT_VHI + (c+0)*ATS + r] = vh; sma[AT_VLO + (c+0)*ATS + r] = vl;
            bf16_split(vv.y, vh, vl);
            sma[AT_VHI + (c+1)*ATS + r] = vh; sma[AT_VLO + (c+1)*ATS + r] = vl;
            bf16_split(vv.z, vh, vl);
            sma[AT_VHI + (c+2)*ATS + r] = vh; sma[AT_VLO + (c+2)*ATS + r] = vl;
            bf16_split(vv.w, vh, vl);
            sma[AT_VHI + (c+3)*ATS + r] = vh; sma[AT_VLO + (c+3)*ATS + r] = vl;
        }
        __syncthreads();

        float sacc[8][4] = {};
        #pragma unroll
        for (int ks = 0; ks < 4; ks++) {
            const int kb = ks * 16;
            uint32_t qh[4], ql[4];
            const __nv_bfloat16* pa = sma + (qw0 + gid)*ATS + kb + tig*2;
            qh[0] = *reinterpret_cast<const uint32_t*>(pa + AT_QHI);
            qh[1] = *reinterpret_cast<const uint32_t*>(pa + AT_QHI + 8*ATS);
            qh[2] = *reinterpret_cast<const uint32_t*>(pa + AT_QHI + 8);
            qh[3] = *reinterpret_cast<const uint32_t*>(pa + AT_QHI + 8*ATS + 8);
            ql[0] = *reinterpret_cast<const uint32_t*>(pa + AT_QLO);
            ql[1] = *reinterpret_cast<const uint32_t*>(pa + AT_QLO + 8*ATS);
            ql[2] = *reinterpret_cast<const uint32_t*>(pa + AT_QLO + 8);
            ql[3] = *reinterpret_cast<const uint32_t*>(pa + AT_QLO + 8*ATS + 8);
            #pragma unroll
            for (int nt = 0; nt < 8; nt++) {
                uint32_t kh[2], kl[2];
                const __nv_bfloat16* pb = sma + (nt*8 + gid)*ATS + kb + tig*2;
                kh[0] = *reinterpret_cast<const uint32_t*>(pb + AT_KHI);
                kh[1] = *reinterpret_cast<const uint32_t*>(pb + AT_KHI + 8);
                kl[0] = *reinterpret_cast<const uint32_t*>(pb + AT_KLO);
                kl[1] = *reinterpret_cast<const uint32_t*>(pb + AT_KLO + 8);
                mma16816(sacc[nt], qh, kh);
                mma16816(sacc[nt], qh, kl);
                mma16816(sacc[nt], ql, kh);
            }
        }

        float mt0 = -1e30f, mt1 = -1e30f;
        #pragma unroll
        for (int nt = 0; nt < 8; nt++) {
            const int c = kt + nt*8 + tig*2;
            const float ka0 = kpm[b*SEQ + c]     ? -1e30f : 0.f;
            const float ka1 = kpm[b*SEQ + c + 1] ? -1e30f : 0.f;
            float2 m0 = *reinterpret_cast<const float2*>(&mask[(size_t)r0g * SEQ + c]);
            float2 m1 = *reinterpret_cast<const float2*>(&mask[(size_t)r1g * SEQ + c]);
            sacc[nt][0] = sacc[nt][0]*scale + m0.x + ka0;
            sacc[nt][1] = sacc[nt][1]*scale + m0.y + ka1;
            sacc[nt][2] = sacc[nt][2]*scale + m1.x + ka0;
            sacc[nt][3] = sacc[nt][3]*scale + m1.y + ka1;
            mt0 = fmaxf(mt0, fmaxf(sacc[nt][0], sacc[nt][1]));
            mt1 = fmaxf(mt1, fmaxf(sacc[nt][2], sacc[nt][3]));
        }
        mt0 = fmaxf(mt0, __shfl_xor_sync(0xffffffff, mt0, 1));
        mt0 = fmaxf(mt0, __shfl_xor_sync(0xffffffff, mt0, 2));
        mt1 = fmaxf(mt1, __shfl_xor_sync(0xffffffff, mt1, 1));
        mt1 = fmaxf(mt1, __shfl_xor_sync(0xffffffff, mt1, 2));

        const float mn0 = fmaxf(mrow0, mt0);
        const float mn1 = fmaxf(mrow1, mt1);
        const float corr0 = __expf(mrow0 - mn0);
        const float corr1 = __expf(mrow1 - mn1);
        mrow0 = mn0; mrow1 = mn1;

        float ps0 = 0.f, ps1 = 0.f;
        #pragma unroll
        for (int nt = 0; nt < 8; nt++) {
            sacc[nt][0] = __expf(sacc[nt][0] - mn0);
            sacc[nt][1] = __expf(sacc[nt][1] - mn0);
            sacc[nt][2] = __expf(sacc[nt][2] - mn1);
            sacc[nt][3] = __expf(sacc[nt][3] - mn1);
            ps0 += sacc[nt][0] + sacc[nt][1];
            ps1 += sacc[nt][2] + sacc[nt][3];
        }
        ps0 += __shfl_xor_sync(0xffffffff, ps0, 1);
        ps0 += __shfl_xor_sync(0xffffffff, ps0, 2);
        ps1 += __shfl_xor_sync(0xffffffff, ps1, 1);
        ps1 += __shfl_xor_sync(0xffffffff, ps1, 2);
        lrow0 = lrow0 * corr0 + ps0;
        lrow1 = lrow1 * corr1 + ps1;

        #pragma unroll
        for (int dt = 0; dt < 8; dt++) {
            ctx[dt][0] *= corr0; ctx[dt][1] *= corr0;
            ctx[dt][2] *= corr1; ctx[dt][3] *= corr1;
        }

        #pragma unroll
        for (int ks = 0; ks < 4; ks++) {
            uint32_t ph[4], pl[4];
            pack_split2(sacc[2*ks][0],   sacc[2*ks][1],   ph[0], pl[0]);
            pack_split2(sacc[2*ks][2],   sacc[2*ks][3],   ph[1], pl[1]);
            pack_split2(sacc[2*ks+1][0], sacc[2*ks+1][1], ph[2], pl[2]);
            pack_split2(sacc[2*ks+1][2], sacc[2*ks+1][3], ph[3], pl[3]);
            #pragma unroll
            for (int dt = 0; dt < 8; dt++) {
                uint32_t vh[2], vl[2];
                const __nv_bfloat16* pb = sma + (dt*8 + gid)*ATS + ks*16 + tig*2;
                vh[0] = *reinterpret_cast<const uint32_t*>(pb + AT_VHI);
                vh[1] = *reinterpret_cast<const uint32_t*>(pb + AT_VHI + 8);
                vl[0] = *reinterpret_cast<const uint32_t*>(pb + AT_VLO);
                vl[1] = *reinterpret_cast<const uint32_t*>(pb + AT_VLO + 8);
                mma16816(ctx[dt], ph, vh);
                mma16816(ctx[dt], ph, vl);
                mma16816(ctx[dt], pl, vh);
            }
        }
        __syncthreads();
    }

    const float inv0 = 1.f / lrow0;
    const float inv1 = 1.f / lrow1;
    #pragma unroll
    for (int dt = 0; dt < 8; dt++) {
        const int col = h*DK + dt*8 + tig*2;
        *reinterpret_cast<float2*>(&Out[(size_t)(b*SEQ + r0g) * DMODEL + col]) =
            make_float2(ctx[dt][0]*inv0, ctx[dt][1]*inv0);
        *reinterpret_cast<float2*>(&Out[(size_t)(b*SEQ + r1g) * DMODEL + col]) =
            make_float2(ctx[dt][2]*inv1, ctx[dt][3]*inv1);
    }
}

// ---------------------------------------------------------------------------
// Launch
// ---------------------------------------------------------------------------
extern "C" void kernel_launch(void* const* d_in, const int* in_sizes, int n_in,
                              void* d_out, int out_size)
{
    const float* x    = (const float*)d_in[0];
    const float* mask = (const float*)d_in[1];
    const unsigned char* kpm = (const unsigned char*)d_in[2];
    const float* g1   = (const float*)d_in[3];
    const float* b1n  = (const float*)d_in[4];
    const float* Wq   = (const float*)d_in[5];
    const float* bq   = (const float*)d_in[6];
    const float* Wk   = (const float*)d_in[7];
    const float* bk   = (const float*)d_in[8];
    const float* Wv   = (const float*)d_in[9];
    const float* bv   = (const float*)d_in[10];
    const float* Wo   = (const float*)d_in[11];
    const float* bo   = (const float*)d_in[12];
    const float* W1   = (const float*)d_in[13];
    const float* b1   = (const float*)d_in[14];
    const float* W2   = (const float*)d_in[15];
    const float* b2   = (const float*)d_in[16];
    float* out = (float*)d_out;

    float *B1, *B2, *B3, *B4;
    __nv_bfloat16 *WHI, *WLO, *AHI, *ALO;
    cudaGetSymbolAddress((void**)&B1, g_buf1);
    cudaGetSymbolAddress((void**)&B2, g_buf2);
    cudaGetSymbolAddress((void**)&B3, g_buf3);
    cudaGetSymbolAddress((void**)&B4, g_buf4);
    cudaGetSymbolAddress((void**)&WHI, g_whi);
    cudaGetSymbolAddress((void**)&WLO, g_wlo);
    cudaGetSymbolAddress((void**)&AHI, g_ahi);
    cudaGetSymbolAddress((void**)&ALO, g_alo);

    cudaFuncSetAttribute(mma_gemm<0>, cudaFuncAttributeMaxDynamicSharedMemorySize, GEMM_SMEM_BYTES);
    cudaFuncSetAttribute(mma_gemm<1>, cudaFuncAttributeMaxDynamicSharedMemorySize, GEMM_SMEM_BYTES);
    cudaFuncSetAttribute(mma_gemm<2>, cudaFuncAttributeMaxDynamicSharedMemorySize, GEMM_SMEM_BYTES);
    cudaFuncSetAttribute(attn_mma_kernel, cudaFuncAttributeMaxDynamicSharedMemorySize, ATTN_SMEM_BYTES);

    const int M = MROWS;
    dim3 gGrid(DMODEL / 128, M / 128);          // (8, 32)
    dim3 tGrid(DMODEL / 32, DMODEL / 32);       // (32, 32)
    dim3 tBlk(32, 8);
    dim3 aGrid(SEQ / 128, BATCH * NHEADS);      // (8, 64)
    const int sGrid = (MROWS * DMODEL) / (256 * 4);   // 4096

    // 1. xq = LN(x)
    ln_kernel<<<M, 256>>>(x, g1, b1n, B1);
    // 2. q = xq@Wq+bq
    split_act<<<sGrid, 256>>>(B1, AHI, ALO);
    tsplit_kernel<<<tGrid, tBlk>>>(Wq, WHI, WLO);
    mma_gemm<0><<<gGrid, 256, GEMM_SMEM_BYTES>>>(AHI, ALO, WHI, WLO, bq, nullptr, B2);
    // 3/4. k = x@Wk+bk ; v = x@Wv+bv   (x split shared)
    split_act<<<sGrid, 256>>>(x, AHI, ALO);
    tsplit_kernel<<<tGrid, tBlk>>>(Wk, WHI, WLO);
    mma_gemm<0><<<gGrid, 256, GEMM_SMEM_BYTES>>>(AHI, ALO, WHI, WLO, bk, nullptr, B3);
    tsplit_kernel<<<tGrid, tBlk>>>(Wv, WHI, WLO);
    mma_gemm<0><<<gGrid, 256, GEMM_SMEM_BYTES>>>(AHI, ALO, WHI, WLO, bv, nullptr, B4);
    // 5. attention -> concat (B1)
    attn_mma_kernel<<<aGrid, 256, ATTN_SMEM_BYTES>>>(B2, B3, B4, mask, kpm, B1);
    // 6. x2 = concat@Wo + bo + x  (B2)
    split_act<<<sGrid, 256>>>(B1, AHI, ALO);
    tsplit_kernel<<<tGrid, tBlk>>>(Wo, WHI, WLO);
    mma_gemm<2><<<gGrid, 256, GEMM_SMEM_BYTES>>>(AHI, ALO, WHI, WLO, bo, x, B2);
    // 7. x3 = LN(x2) (B3)
    ln_kernel<<<M, 256>>>(B2, g1, b1n, B3);
    // 8. h = relu(x3@W1 + b1) (B4)
    split_act<<<sGrid, 256>>>(B3, AHI, ALO);
    tsplit_kernel<<<tGrid, tBlk>>>(W1, WHI, WLO);
    mma_gemm<1><<<gGrid, 256, GEMM_SMEM_BYTES>>>(AHI, ALO, WHI, WLO, b1, nullptr, B4);
    // 9. out = x3 + h@W2 + b2
    split_act<<<sGrid, 256>>>(B4, AHI, ALO);
    tsplit_kernel<<<tGrid, tBlk>>>(W2, WHI, WLO);
    mma_gemm<2><<<gGrid, 256, GEMM_SMEM_BYTES>>>(AHI, ALO, WHI, WLO, b2, B3, out);
}

// round 7
// speedup vs baseline: 2.3810x; 1.2867x over previous
#include <cuda_runtime.h>
#include <cuda_bf16.h>
#include <math.h>
#include <stdint.h>

// Problem constants
#define BATCH 4
#define SEQ   1024
#define DMODEL 1024
#define NHEADS 16
#define DK    64
#define MROWS (BATCH * SEQ)       // 4096
#define LN_EPS 1e-5f

// ---------------------------------------------------------------------------
// Scratch buffers (allocation-free rule: __device__ globals)
// ---------------------------------------------------------------------------
__device__ float g_buf1[MROWS * DMODEL];   // xq -> concat
__device__ float g_buf2[MROWS * DMODEL];   // q  -> x2
__device__ float g_buf3[MROWS * DMODEL];   // k  -> x3
__device__ float g_buf4[MROWS * DMODEL];   // v  -> h
__device__ __nv_bfloat16 g_whi[DMODEL * DMODEL];   // W^T split hi  [N,K]
__device__ __nv_bfloat16 g_wlo[DMODEL * DMODEL];   // W^T split lo  [N,K]
__device__ __nv_bfloat16 g_ahi[MROWS * DMODEL];    // activation split hi (also Q)
__device__ __nv_bfloat16 g_alo[MROWS * DMODEL];    // activation split lo
__device__ __nv_bfloat16 g_khi[MROWS * DMODEL];    // K split hi
__device__ __nv_bfloat16 g_klo[MROWS * DMODEL];    // K split lo
__device__ __nv_bfloat16 g_vhi[MROWS * DMODEL];    // V split hi
__device__ __nv_bfloat16 g_vlo[MROWS * DMODEL];    // V split lo

// ---------------------------------------------------------------------------
// PTX helpers
// ---------------------------------------------------------------------------
__device__ __forceinline__ uint32_t smem_to_u32(const void* smem_ptr) {
    uint32_t addr;
    asm("{ .reg .u64 tmp; cvta.to.shared.u64 tmp, %1; cvt.u32.u64 %0, tmp; }"
        : "=r"(addr) : "l"(smem_ptr));
    return addr;
}

__device__ __forceinline__ void mma16816(float* d, const uint32_t* a, const uint32_t* b)
{
    asm volatile(
        "mma.sync.aligned.m16n8k16.row.col.f32.bf16.bf16.f32 "
        "{%0,%1,%2,%3}, {%4,%5,%6,%7}, {%8,%9}, {%0,%1,%2,%3};"
        : "+f"(d[0]), "+f"(d[1]), "+f"(d[2]), "+f"(d[3])
        : "r"(a[0]), "r"(a[1]), "r"(a[2]), "r"(a[3]), "r"(b[0]), "r"(b[1]));
}

__device__ __forceinline__ void ldmx4(uint32_t* r, uint32_t addr) {
    asm volatile("ldmatrix.sync.aligned.m8n8.x4.shared.b16 {%0,%1,%2,%3}, [%4];"
        : "=r"(r[0]), "=r"(r[1]), "=r"(r[2]), "=r"(r[3]) : "r"(addr));
}
__device__ __forceinline__ void ldmx2(uint32_t* r, uint32_t addr) {
    asm volatile("ldmatrix.sync.aligned.m8n8.x2.shared.b16 {%0,%1}, [%2];"
        : "=r"(r[0]), "=r"(r[1]) : "r"(addr));
}
__device__ __forceinline__ void ldmx2t(uint32_t* r, uint32_t addr) {
    asm volatile("ldmatrix.sync.aligned.m8n8.x2.trans.shared.b16 {%0,%1}, [%2];"
        : "=r"(r[0]), "=r"(r[1]) : "r"(addr));
}

__device__ __forceinline__ void cp16(uint32_t dst, const void* src) {
    asm volatile("cp.async.cg.shared.global [%0], [%1], 16;" :: "r"(dst), "l"(src));
}
#define CP_COMMIT() asm volatile("cp.async.commit_group;" ::: "memory")
#define CP_WAIT0()  asm volatile("cp.async.wait_group 0;" ::: "memory")

__device__ __forceinline__ void bf16_split(float a, __nv_bfloat16& hi, __nv_bfloat16& lo)
{
    hi = __float2bfloat16_rn(a);
    lo = __float2bfloat16_rn(a - __bfloat162float(hi));
}

__device__ __forceinline__ void pack_split2(float f0, float f1, uint32_t& hi, uint32_t& lo)
{
    __nv_bfloat16 h0, l0, h1, l1;
    bf16_split(f0, h0, l0);
    bf16_split(f1, h1, l1);
    __nv_bfloat162 hv(h0, h1), lv(l0, l1);
    hi = *reinterpret_cast<uint32_t*>(&hv);
    lo = *reinterpret_cast<uint32_t*>(&lv);
}

// ---------------------------------------------------------------------------
// LayerNorm
// ---------------------------------------------------------------------------
__global__ void __launch_bounds__(256) ln_kernel(const float* __restrict__ X,
                                                 const float* __restrict__ gamma,
                                                 const float* __restrict__ beta,
                                                 float* __restrict__ Y)
{
    const int row = blockIdx.x;
    const int tid = threadIdx.x;
    const float4* x4 = reinterpret_cast<const float4*>(X + (size_t)row * DMODEL);
    float4 a = x4[tid];

    float s  = a.x + a.y + a.z + a.w;
    float ss = a.x*a.x + a.y*a.y + a.z*a.z + a.w*a.w;

    #pragma unroll
    for (int off = 16; off > 0; off >>= 1) {
        s  += __shfl_xor_sync(0xffffffff, s,  off);
        ss += __shfl_xor_sync(0xffffffff, ss, off);
    }
    __shared__ float red_s[8], red_ss[8];
    __shared__ float s_mu, s_inv;
    int wid = tid >> 5, lane = tid & 31;
    if (lane == 0) { red_s[wid] = s; red_ss[wid] = ss; }
    __syncthreads();
    if (tid == 0) {
        float ts = 0.f, tss = 0.f;
        #pragma unroll
        for (int i = 0; i < 8; i++) { ts += red_s[i]; tss += red_ss[i]; }
        float mu  = ts * (1.0f / DMODEL);
        float var = tss * (1.0f / DMODEL) - mu * mu;
        s_mu  = mu;
        s_inv = rsqrtf(var + LN_EPS);
    }
    __syncthreads();
    float mu = s_mu, inv = s_inv;

    float4 g4 = reinterpret_cast<const float4*>(gamma)[tid];
    float4 b4 = reinterpret_cast<const float4*>(beta)[tid];
    float4 o;
    o.x = (a.x - mu) * inv * g4.x + b4.x;
    o.y = (a.y - mu) * inv * g4.y + b4.y;
    o.z = (a.z - mu) * inv * g4.z + b4.z;
    o.w = (a.w - mu) * inv * g4.w + b4.w;
    reinterpret_cast<float4*>(Y + (size_t)row * DMODEL)[tid] = o;
}

// ---------------------------------------------------------------------------
// Activation split: fp32 -> bf16 hi/lo (elementwise)
// ---------------------------------------------------------------------------
__global__ void __launch_bounds__(256) split_act(const float* __restrict__ X,
                                                 __nv_bfloat16* __restrict__ H,
                                                 __nv_bfloat16* __restrict__ L)
{
    const int i = (blockIdx.x * 256 + threadIdx.x) * 4;
    float4 v = *reinterpret_cast<const float4*>(X + i);
    __nv_bfloat16 h0,l0,h1,l1,h2,l2,h3,l3;
    bf16_split(v.x, h0, l0); bf16_split(v.y, h1, l1);
    bf16_split(v.z, h2, l2); bf16_split(v.w, h3, l3);
    __nv_bfloat162 hv0(h0, h1), hv1(h2, h3), lv0(l0, l1), lv1(l2, l3);
    reinterpret_cast<__nv_bfloat162*>(H + i)[0] = hv0;
    reinterpret_cast<__nv_bfloat162*>(H + i)[1] = hv1;
    reinterpret_cast<__nv_bfloat162*>(L + i)[0] = lv0;
    reinterpret_cast<__nv_bfloat162*>(L + i)[1] = lv1;
}

// ---------------------------------------------------------------------------
// Transpose + split: W[K,N] fp32 row-major -> Whi/Wlo[N,K] bf16 row-major
// ---------------------------------------------------------------------------
__global__ void __launch_bounds__(256) tsplit_kernel(const float* __restrict__ W,
                                                     __nv_bfloat16* __restrict__ Bh,
                                                     __nv_bfloat16* __restrict__ Bl)
{
    __shared__ float t[32][33];
    const int n0 = blockIdx.x * 32, k0 = blockIdx.y * 32;
    const int tx = threadIdx.x, ty = threadIdx.y;
    #pragma unroll
    for (int r = 0; r < 4; r++)
        t[ty + 8*r][tx] = W[(size_t)(k0 + ty + 8*r) * DMODEL + n0 + tx];
    __syncthreads();
    #pragma unroll
    for (int r = 0; r < 4; r++) {
        int n = n0 + ty + 8*r;
        float a = t[tx][ty + 8*r];
        __nv_bfloat16 hi, lo;
        bf16_split(a, hi, lo);
        Bh[(size_t)n * DMODEL + k0 + tx] = hi;
        Bl[(size_t)n * DMODEL + k0 + tx] = lo;
    }
}

// ---------------------------------------------------------------------------
// Tensor-core split-bf16 GEMM, cp.async 2-stage pipeline, K-chunk 64.
// C[M,N] = A[M,K] @ W ; A pre-split (Ah,Al bf16 [M,K]); W pre-split ([N,K]).
// CTA tile 128x128, 8 warps (2x4), warp tile 64x32, mma m16n8k16.
// 3 MMAs per k-step: hi*hi + hi*lo + lo*hi.
// EPI: 0 = bias, 1 = bias+relu, 2 = bias+residual
// ---------------------------------------------------------------------------
#define GPAD 72                          // smem row stride in bf16 (64 + 8)
#define S_AHI 0
#define S_ALO (128 * GPAD)
#define S_BHI (2 * 128 * GPAD)
#define S_BLO (3 * 128 * GPAD)
#define STAGE_ELEMS (4 * 128 * GPAD)     // 36864 bf16
#define GEMM_SMEM_BYTES (2 * STAGE_ELEMS * 2)   // 147456 B
#define NCH (DMODEL / 64)                // 16 chunks

template<int EPI>
__global__ void __launch_bounds__(256) mma_gemm(const __nv_bfloat16* __restrict__ Ah,
                                                const __nv_bfloat16* __restrict__ Al,
                                                const __nv_bfloat16* __restrict__ Wh,
                                                const __nv_bfloat16* __restrict__ Wl,
                                                const float* __restrict__ bias,
                                                const float* __restrict__ resid,
                                                float* __restrict__ C)
{
    extern __shared__ __nv_bfloat16 sm[];
    const uint32_t smb = smem_to_u32(sm);
    const int tid  = threadIdx.x;
    const int wid  = tid >> 5;
    const int lane = tid & 31;
    const int gid  = lane >> 2;
    const int tig  = lane & 3;
    const int g8   = lane >> 3;     // 0..3
    const int r8   = lane & 7;
    const int brow = blockIdx.y * 128;
    const int bcol = blockIdx.x * 128;
    const int m0   = (wid >> 2) * 64;
    const int n0   = (wid & 3) * 32;

    const __nv_bfloat16* gsrc[4] = {
        Ah + (size_t)brow * DMODEL,
        Al + (size_t)brow * DMODEL,
        Wh + (size_t)bcol * DMODEL,
        Wl + (size_t)bcol * DMODEL };

    // cp.async fill of one 64-wide chunk: 4 arrays x 128 rows x 8 units = 16/thread
    auto issue = [&](int chunk, int stage) {
        const int k0 = chunk * 64;
        #pragma unroll
        for (int j = 0; j < 16; j++) {
            const int arr = j >> 2;
            const int rem = ((j & 3) << 8) + tid;          // 0..1023
            const int r   = rem >> 3;                      // 0..127
            const int c   = (rem & 7) * 8;                 // 0..56
            const __nv_bfloat16* src = gsrc[arr] + (size_t)r * DMODEL + k0 + c;
            const uint32_t dst = smb +
                (uint32_t)(stage * STAGE_ELEMS + arr * (128 * GPAD) + r * GPAD + c) * 2;
            cp16(dst, src);
        }
        CP_COMMIT();
    };

    float acc[4][4][4] = {};

    issue(0, 0);
    for (int i = 0; i < NCH; i++) {
        CP_WAIT0();
        __syncthreads();
        if (i + 1 < NCH) issue(i + 1, (i + 1) & 1);

        const uint32_t sb = smb + (uint32_t)((i & 1) * STAGE_ELEMS) * 2;
        #pragma unroll
        for (int s = 0; s < 4; s++) {
            const int kb = s * 16;
            uint32_t ah[4][4], al[4][4];
            #pragma unroll
            for (int mf = 0; mf < 4; mf++) {
                const int row = m0 + mf*16 + ((g8 & 1) << 3) + r8;
                const int col = kb + ((g8 >> 1) << 3);
                ldmx4(ah[mf], sb + (uint32_t)(S_AHI + row*GPAD + col) * 2);
                ldmx4(al[mf], sb + (uint32_t)(S_ALO + row*GPAD + col) * 2);
            }
            #pragma unroll
            for (int nf = 0; nf < 4; nf++) {
                const int rowB = n0 + nf*8 + r8;
                const int colB = kb + ((g8 & 1) << 3);
                uint32_t bh[2], bl[2];
                ldmx2(bh, sb + (uint32_t)(S_BHI + rowB*GPAD + colB) * 2);
                ldmx2(bl, sb + (uint32_t)(S_BLO + rowB*GPAD + colB) * 2);
                #pragma unroll
                for (int mf = 0; mf < 4; mf++) {
                    mma16816(acc[mf][nf], ah[mf], bh);
                    mma16816(acc[mf][nf], ah[mf], bl);
                    mma16816(acc[mf][nf], al[mf], bh);
                }
            }
        }
        __syncthreads();
    }

    // ---- epilogue ----
    #pragma unroll
    for (int mf = 0; mf < 4; mf++) {
        #pragma unroll
        for (int nf = 0; nf < 4; nf++) {
            const int row0 = brow + m0 + mf*16 + gid;
            const int col  = bcol + n0 + nf*8 + tig*2;
            float2 bv = *reinterpret_cast<const float2*>(&bias[col]);
            float o0 = acc[mf][nf][0] + bv.x;
            float o1 = acc[mf][nf][1] + bv.y;
            float o2 = acc[mf][nf][2] + bv.x;
            float o3 = acc[mf][nf][3] + bv.y;
            if (EPI == 1) {
                o0 = fmaxf(o0, 0.f); o1 = fmaxf(o1, 0.f);
                o2 = fmaxf(o2, 0.f); o3 = fmaxf(o3, 0.f);
            }
            if (EPI == 2) {
                float2 r0 = *reinterpret_cast<const float2*>(&resid[(size_t)row0 * DMODEL + col]);
                float2 r1 = *reinterpret_cast<const float2*>(&resid[(size_t)(row0+8) * DMODEL + col]);
                o0 += r0.x; o1 += r0.y; o2 += r1.x; o3 += r1.y;
            }
            *reinterpret_cast<float2*>(&C[(size_t)row0 * DMODEL + col])      = make_float2(o0, o1);
            *reinterpret_cast<float2*>(&C[(size_t)(row0+8) * DMODEL + col])  = make_float2(o2, o3);
        }
    }
}

// ---------------------------------------------------------------------------
// Tensor-core flash attention v2: pre-split Q/K/V, cp.async double-buffered
// K/V tiles, ldmatrix fragments, ldmatrix.trans for V (no scatter transpose).
// Q tile 128, K tile 64, 8 warps x 16 q-rows, dk = 64.
// ---------------------------------------------------------------------------
#define ATS 72
#define AQ_HI 0
#define AQ_LO (128 * ATS)
#define AKV_BASE (2 * 128 * ATS)
#define KV_STAGE (4 * 64 * ATS)
#define KV_KHI 0
#define KV_KLO (64 * ATS)
#define KV_VHI (2 * 64 * ATS)
#define KV_VLO (3 * 64 * ATS)
#define ATTN_SMEM_BYTES ((AKV_BASE + 2 * KV_STAGE) * 2)   // 110592 B
#define NKT (SEQ / 64)   // 16 key tiles

__global__ void __launch_bounds__(256) attn_mma_kernel(
    const __nv_bfloat16* __restrict__ Qh, const __nv_bfloat16* __restrict__ Ql,
    const __nv_bfloat16* __restrict__ Kh, const __nv_bfloat16* __restrict__ Kl,
    const __nv_bfloat16* __restrict__ Vh, const __nv_bfloat16* __restrict__ Vl,
    const float* __restrict__ mask,
    const unsigned char* __restrict__ kpm,
    float* __restrict__ Out)
{
    extern __shared__ __nv_bfloat16 sma[];
    const uint32_t smb = smem_to_u32(sma);
    const int tid  = threadIdx.x;
    const int wid  = tid >> 5;
    const int lane = tid & 31;
    const int gid  = lane >> 2;
    const int tig  = lane & 3;
    const int g8   = lane >> 3;
    const int r8   = lane & 7;
    const int bh   = blockIdx.y;
    const int b    = bh / NHEADS;
    const int h    = bh % NHEADS;
    const int q0   = blockIdx.x * 128;
    const int qw0  = wid * 16;
    const float scale = 0.125f;

    const __nv_bfloat16* qsrc[2] = {
        Qh + (size_t)(b*SEQ + q0) * DMODEL + h*DK,
        Ql + (size_t)(b*SEQ + q0) * DMODEL + h*DK };
    const __nv_bfloat16* kvsrc[4] = {
        Kh + (size_t)(b*SEQ) * DMODEL + h*DK,
        Kl + (size_t)(b*SEQ) * DMODEL + h*DK,
        Vh + (size_t)(b*SEQ) * DMODEL + h*DK,
        Vl + (size_t)(b*SEQ) * DMODEL + h*DK };

    // Q fill: 2 arrays x 128 rows x 8 units = 2048 -> 8/thread
    {
        #pragma unroll
        for (int j = 0; j < 8; j++) {
            const int arr = j >> 2;
            const int rem = ((j & 3) << 8) + tid;      // 0..1023
            const int r   = rem >> 3;
            const int c   = (rem & 7) * 8;
            const uint32_t dst = smb +
                (uint32_t)((arr ? AQ_LO : AQ_HI) + r*ATS + c) * 2;
            cp16(dst, qsrc[arr] + (size_t)r * DMODEL + c);
        }
    }
    // KV fill: 4 arrays x 64 rows x 8 units = 2048 -> 8/thread
    auto issue_kv = [&](int kt, int stage) {
        #pragma unroll
        for (int j = 0; j < 8; j++) {
            const int arr = j >> 1;
            const int rem = ((j & 1) << 8) + tid;      // 0..511
            const int r   = rem >> 3;
            const int c   = (rem & 7) * 8;
            const uint32_t dst = smb +
                (uint32_t)(AKV_BASE + stage*KV_STAGE + arr*(64*ATS) + r*ATS + c) * 2;
            cp16(dst, kvsrc[arr] + (size_t)(kt*64 + r) * DMODEL + c);
        }
        CP_COMMIT();
    };
    issue_kv(0, 0);   // committed together with Q fill

    float ctx[8][4] = {};
    float mrow0 = -1e30f, mrow1 = -1e30f;
    float lrow0 = 0.f,    lrow1 = 0.f;

    const int r0g = q0 + qw0 + gid;
    const int r1g = r0g + 8;

    for (int i = 0; i < NKT; i++) {
        CP_WAIT0();
        __syncthreads();
        if (i + 1 < NKT) issue_kv(i + 1, (i + 1) & 1);

        const uint32_t kvb = smb + (uint32_t)(AKV_BASE + (i & 1)*KV_STAGE) * 2;
        const int kt = i * 64;

        // ---- S = Q K^T (split, 3 MMAs/k-step) ----
        float sacc[8][4] = {};
        #pragma unroll
        for (int ks = 0; ks < 4; ks++) {
            const int kb = ks * 16;
            uint32_t qh[4], ql[4];
            {
                const int row = qw0 + ((g8 & 1) << 3) + r8;
                const int col = kb + ((g8 >> 1) << 3);
                ldmx4(qh, smb + (uint32_t)(AQ_HI + row*ATS + col) * 2);
                ldmx4(ql, smb + (uint32_t)(AQ_LO + row*ATS + col) * 2);
            }
            #pragma unroll
            for (int nt = 0; nt < 8; nt++) {
                const int rowB = nt*8 + r8;
                const int colB = kb + ((g8 & 1) << 3);
                uint32_t kh[2], kl[2];
                ldmx2(kh, kvb + (uint32_t)(KV_KHI + rowB*ATS + colB) * 2);
                ldmx2(kl, kvb + (uint32_t)(KV_KLO + rowB*ATS + colB) * 2);
                mma16816(sacc[nt], qh, kh);
                mma16816(sacc[nt], qh, kl);
                mma16816(sacc[nt], ql, kh);
            }
        }

        // ---- scale + masks + online softmax ----
        float mt0 = -1e30f, mt1 = -1e30f;
        #pragma unroll
        for (int nt = 0; nt < 8; nt++) {
            const int c = kt + nt*8 + tig*2;
            const float ka0 = kpm[b*SEQ + c]     ? -1e30f : 0.f;
            const float ka1 = kpm[b*SEQ + c + 1] ? -1e30f : 0.f;
            float2 m0 = *reinterpret_cast<const float2*>(&mask[(size_t)r0g * SEQ + c]);
            float2 m1 = *reinterpret_cast<const float2*>(&mask[(size_t)r1g * SEQ + c]);
            sacc[nt][0] = sacc[nt][0]*scale + m0.x + ka0;
            sacc[nt][1] = sacc[nt][1]*scale + m0.y + ka1;
            sacc[nt][2] = sacc[nt][2]*scale + m1.x + ka0;
            sacc[nt][3] = sacc[nt][3]*scale + m1.y + ka1;
            mt0 = fmaxf(mt0, fmaxf(sacc[nt][0], sacc[nt][1]));
            mt1 = fmaxf(mt1, fmaxf(sacc[nt][2], sacc[nt][3]));
        }
        mt0 = fmaxf(mt0, __shfl_xor_sync(0xffffffff, mt0, 1));
        mt0 = fmaxf(mt0, __shfl_xor_sync(0xffffffff, mt0, 2));
        mt1 = fmaxf(mt1, __shfl_xor_sync(0xffffffff, mt1, 1));
        mt1 = fmaxf(mt1, __shfl_xor_sync(0xffffffff, mt1, 2));

        const float mn0 = fmaxf(mrow0, mt0);
        const float mn1 = fmaxf(mrow1, mt1);
        const float corr0 = __expf(mrow0 - mn0);
        const float corr1 = __expf(mrow1 - mn1);
        mrow0 = mn0; mrow1 = mn1;

        float ps0 = 0.f, ps1 = 0.f;
        #pragma unroll
        for (int nt = 0; nt < 8; nt++) {
            sacc[nt][0] = __expf(sacc[nt][0] - mn0);
            sacc[nt][1] = __expf(sacc[nt][1] - mn0);
            sacc[nt][2] = __expf(sacc[nt][2] - mn1);
            sacc[nt][3] = __expf(sacc[nt][3] - mn1);
            ps0 += sacc[nt][0] + sacc[nt][1];
            ps1 += sacc[nt][2] + sacc[nt][3];
        }
        ps0 += __shfl_xor_sync(0xffffffff, ps0, 1);
        ps0 += __shfl_xor_sync(0xffffffff, ps0, 2);
        ps1 += __shfl_xor_sync(0xffffffff, ps1, 1);
        ps1 += __shfl_xor_sync(0xffffffff, ps1, 2);
        lrow0 = lrow0 * corr0 + ps0;
        lrow1 = lrow1 * corr1 + ps1;

        #pragma unroll
        for (int dt = 0; dt < 8; dt++) {
            ctx[dt][0] *= corr0; ctx[dt][1] *= corr0;
            ctx[dt][2] *= corr1; ctx[dt][3] *= corr1;
        }

        // ---- PV: P packed from accumulators; V via ldmatrix.trans ----
        #pragma unroll
        for (int ks = 0; ks < 4; ks++) {
            uint32_t ph[4], pl[4];
            pack_split2(sacc[2*ks][0],   sacc[2*ks][1],   ph[0], pl[0]);
            pack_split2(sacc[2*ks][2],   sacc[2*ks][3],   ph[1], pl[1]);
            pack_split2(sacc[2*ks+1][0], sacc[2*ks+1][1], ph[2], pl[2]);
            pack_split2(sacc[2*ks+1][2], sacc[2*ks+1][3], ph[3], pl[3]);
            const int rowV = ks*16 + ((g8 & 1) << 3) + r8;   // key row (lanes 0-15)
            #pragma unroll
            for (int dt = 0; dt < 8; dt++) {
                uint32_t vh[2], vl[2];
                ldmx2t(vh, kvb + (uint32_t)(KV_VHI + rowV*ATS + dt*8) * 2);
                ldmx2t(vl, kvb + (uint32_t)(KV_VLO + rowV*ATS + dt*8) * 2);
                mma16816(ctx[dt], ph, vh);
                mma16816(ctx[dt], ph, vl);
                mma16816(ctx[dt], pl, vh);
            }
        }
        __syncthreads();
    }

    const float inv0 = 1.f / lrow0;
    const float inv1 = 1.f / lrow1;
    #pragma unroll
    for (int dt = 0; dt < 8; dt++) {
        const int col = h*DK + dt*8 + tig*2;
        *reinterpret_cast<float2*>(&Out[(size_t)(b*SEQ + r0g) * DMODEL + col]) =
            make_float2(ctx[dt][0]*inv0, ctx[dt][1]*inv0);
        *reinterpret_cast<float2*>(&Out[(size_t)(b*SEQ + r1g) * DMODEL + col]) =
            make_float2(ctx[dt][2]*inv1, ctx[dt][3]*inv1);
    }
}

// ---------------------------------------------------------------------------
// Launch
// ---------------------------------------------------------------------------
extern "C" void kernel_launch(void* const* d_in, const int* in_sizes, int n_in,
                              void* d_out, int out_size)
{
    const float* x    = (const float*)d_in[0];
    const float* mask = (const float*)d_in[1];
    const unsigned char* kpm = (const unsigned char*)d_in[2];
    const float* g1   = (const float*)d_in[3];
    const float* b1n  = (const float*)d_in[4];
    const float* Wq   = (const float*)d_in[5];
    const float* bq   = (const float*)d_in[6];
    const float* Wk   = (const float*)d_in[7];
    const float* bk   = (const float*)d_in[8];
    const float* Wv   = (const float*)d_in[9];
    const float* bv   = (const float*)d_in[10];
    const float* Wo   = (const float*)d_in[11];
    const float* bo   = (const float*)d_in[12];
    const float* W1   = (const float*)d_in[13];
    const float* b1   = (const float*)d_in[14];
    const float* W2   = (const float*)d_in[15];
    const float* b2   = (const float*)d_in[16];
    float* out = (float*)d_out;

    float *B1, *B2, *B3, *B4;
    __nv_bfloat16 *WHI, *WLO, *AHI, *ALO, *KHI, *KLO, *VHI, *VLO;
    cudaGetSymbolAddress((void**)&B1, g_buf1);
    cudaGetSymbolAddress((void**)&B2, g_buf2);
    cudaGetSymbolAddress((void**)&B3, g_buf3);
    cudaGetSymbolAddress((void**)&B4, g_buf4);
    cudaGetSymbolAddress((void**)&WHI, g_whi);
    cudaGetSymbolAddress((void**)&WLO, g_wlo);
    cudaGetSymbolAddress((void**)&AHI, g_ahi);
    cudaGetSymbolAddress((void**)&ALO, g_alo);
    cudaGetSymbolAddress((void**)&KHI, g_khi);
    cudaGetSymbolAddress((void**)&KLO, g_klo);
    cudaGetSymbolAddress((void**)&VHI, g_vhi);
    cudaGetSymbolAddress((void**)&VLO, g_vlo);

    cudaFuncSetAttribute(mma_gemm<0>, cudaFuncAttributeMaxDynamicSharedMemorySize, GEMM_SMEM_BYTES);
    cudaFuncSetAttribute(mma_gemm<1>, cudaFuncAttributeMaxDynamicSharedMemorySize, GEMM_SMEM_BYTES);
    cudaFuncSetAttribute(mma_gemm<2>, cudaFuncAttributeMaxDynamicSharedMemorySize, GEMM_SMEM_BYTES);
    cudaFuncSetAttribute(attn_mma_kernel, cudaFuncAttributeMaxDynamicSharedMemorySize, ATTN_SMEM_BYTES);

    const int M = MROWS;
    dim3 gGrid(DMODEL / 128, M / 128);          // (8, 32)
    dim3 tGrid(DMODEL / 32, DMODEL / 32);       // (32, 32)
    dim3 tBlk(32, 8);
    dim3 aGrid(SEQ / 128, BATCH * NHEADS);      // (8, 64)
    const int sGrid = (MROWS * DMODEL) / (256 * 4);   // 4096

    // 1. xq = LN(x)
    ln_kernel<<<M, 256>>>(x, g1, b1n, B1);
    // 2. q = xq@Wq+bq
    split_act<<<sGrid, 256>>>(B1, AHI, ALO);
    tsplit_kernel<<<tGrid, tBlk>>>(Wq, WHI, WLO);
    mma_gemm<0><<<gGrid, 256, GEMM_SMEM_BYTES>>>(AHI, ALO, WHI, WLO, bq, nullptr, B2);
    // 3/4. k = x@Wk+bk ; v = x@Wv+bv   (x split shared)
    split_act<<<sGrid, 256>>>(x, AHI, ALO);
    tsplit_kernel<<<tGrid, tBlk>>>(Wk, WHI, WLO);
    mma_gemm<0><<<gGrid, 256, GEMM_SMEM_BYTES>>>(AHI, ALO, WHI, WLO, bk, nullptr, B3);
    tsplit_kernel<<<tGrid, tBlk>>>(Wv, WHI, WLO);
    mma_gemm<0><<<gGrid, 256, GEMM_SMEM_BYTES>>>(AHI, ALO, WHI, WLO, bv, nullptr, B4);
    // 5. pre-split q/k/v, attention -> concat (B1)
    split_act<<<sGrid, 256>>>(B2, AHI, ALO);     // Q split (AHI/ALO free now)
    split_act<<<sGrid, 256>>>(B3, KHI, KLO);
    split_act<<<sGrid, 256>>>(B4, VHI, VLO);
    attn_mma_kernel<<<aGrid, 256, ATTN_SMEM_BYTES>>>(AHI, ALO, KHI, KLO, VHI, VLO,
                                                     mask, kpm, B1);
    // 6. x2 = concat@Wo + bo + x  (B2)
    split_act<<<sGrid, 256>>>(B1, AHI, ALO);
    tsplit_kernel<<<tGrid, tBlk>>>(Wo, WHI, WLO);
    mma_gemm<2><<<gGrid, 256, GEMM_SMEM_BYTES>>>(AHI, ALO, WHI, WLO, bo, x, B2);
    // 7. x3 = LN(x2) (B3)
    ln_kernel<<<M, 256>>>(B2, g1, b1n, B3);
    // 8. h = relu(x3@W1 + b1) (B4)
    split_act<<<sGrid, 256>>>(B3, AHI, ALO);
    tsplit_kernel<<<tGrid, tBlk>>>(W1, WHI, WLO);
    mma_gemm<1><<<gGrid, 256, GEMM_SMEM_BYTES>>>(AHI, ALO, WHI, WLO, b1, nullptr, B4);
    // 9. out = x3 + h@W2 + b2
    split_act<<<sGrid, 256>>>(B4, AHI, ALO);
    tsplit_kernel<<<tGrid, tBlk>>>(W2, WHI, WLO);
    mma_gemm<2><<<gGrid, 256, GEMM_SMEM_BYTES>>>(AHI, ALO, WHI, WLO, b2, B3, out);
}

// round 8
// speedup vs baseline: 2.4747x; 1.0393x over previous
#include <cuda_runtime.h>
#include <cuda_bf16.h>
#include <math.h>
#include <stdint.h>

// Problem constants
#define BATCH 4
#define SEQ   1024
#define DMODEL 1024
#define NHEADS 16
#define DK    64
#define MROWS (BATCH * SEQ)       // 4096
#define LN_EPS 1e-5f

// ---------------------------------------------------------------------------
// Scratch buffers (allocation-free rule: __device__ globals)
// ---------------------------------------------------------------------------
__device__ float g_buf2[MROWS * DMODEL];           // x2 (post-attn residual)
__device__ float g_buf3[MROWS * DMODEL];           // x3 (post-LN2)
__device__ __nv_bfloat16 g_whi[DMODEL * DMODEL];   // W^T split hi  [N,K]
__device__ __nv_bfloat16 g_wlo[DMODEL * DMODEL];   // W^T split lo  [N,K]
__device__ __nv_bfloat16 g_ahi[MROWS * DMODEL];    // A-operand staging hi
__device__ __nv_bfloat16 g_alo[MROWS * DMODEL];    // A-operand staging lo
__device__ __nv_bfloat16 g_qhi[MROWS * DMODEL];    // q / ff-h split hi
__device__ __nv_bfloat16 g_qlo[MROWS * DMODEL];
__device__ __nv_bfloat16 g_khi[MROWS * DMODEL];    // k split hi
__device__ __nv_bfloat16 g_klo[MROWS * DMODEL];
__device__ __nv_bfloat16 g_vhi[MROWS * DMODEL];    // v split hi
__device__ __nv_bfloat16 g_vlo[MROWS * DMODEL];

// ---------------------------------------------------------------------------
// PTX helpers
// ---------------------------------------------------------------------------
__device__ __forceinline__ uint32_t smem_to_u32(const void* smem_ptr) {
    uint32_t addr;
    asm("{ .reg .u64 tmp; cvta.to.shared.u64 tmp, %1; cvt.u32.u64 %0, tmp; }"
        : "=r"(addr) : "l"(smem_ptr));
    return addr;
}

__device__ __forceinline__ void mma16816(float* d, const uint32_t* a, const uint32_t* b)
{
    asm volatile(
        "mma.sync.aligned.m16n8k16.row.col.f32.bf16.bf16.f32 "
        "{%0,%1,%2,%3}, {%4,%5,%6,%7}, {%8,%9}, {%0,%1,%2,%3};"
        : "+f"(d[0]), "+f"(d[1]), "+f"(d[2]), "+f"(d[3])
        : "r"(a[0]), "r"(a[1]), "r"(a[2]), "r"(a[3]), "r"(b[0]), "r"(b[1]));
}

__device__ __forceinline__ void ldmx4(uint32_t* r, uint32_t addr) {
    asm volatile("ldmatrix.sync.aligned.m8n8.x4.shared.b16 {%0,%1,%2,%3}, [%4];"
        : "=r"(r[0]), "=r"(r[1]), "=r"(r[2]), "=r"(r[3]) : "r"(addr));
}
__device__ __forceinline__ void ldmx2(uint32_t* r, uint32_t addr) {
    asm volatile("ldmatrix.sync.aligned.m8n8.x2.shared.b16 {%0,%1}, [%2];"
        : "=r"(r[0]), "=r"(r[1]) : "r"(addr));
}
__device__ __forceinline__ void ldmx2t(uint32_t* r, uint32_t addr) {
    asm volatile("ldmatrix.sync.aligned.m8n8.x2.trans.shared.b16 {%0,%1}, [%2];"
        : "=r"(r[0]), "=r"(r[1]) : "r"(addr));
}

__device__ __forceinline__ void cp16(uint32_t dst, const void* src) {
    asm volatile("cp.async.cg.shared.global [%0], [%1], 16;" :: "r"(dst), "l"(src));
}
#define CP_COMMIT() asm volatile("cp.async.commit_group;" ::: "memory")
#define CP_WAIT0()  asm volatile("cp.async.wait_group 0;" ::: "memory")

__device__ __forceinline__ void bf16_split(float a, __nv_bfloat16& hi, __nv_bfloat16& lo)
{
    hi = __float2bfloat16_rn(a);
    lo = __float2bfloat16_rn(a - __bfloat162float(hi));
}

__device__ __forceinline__ void pack_split2(float f0, float f1, uint32_t& hi, uint32_t& lo)
{
    __nv_bfloat16 h0, l0, h1, l1;
    bf16_split(f0, h0, l0);
    bf16_split(f1, h1, l1);
    __nv_bfloat162 hv(h0, h1), lv(l0, l1);
    hi = *reinterpret_cast<uint32_t*>(&hv);
    lo = *reinterpret_cast<uint32_t*>(&lv);
}

// ---------------------------------------------------------------------------
// LayerNorm with optional fused fp32 / split-bf16 outputs.
// MODE bit0: write fp32 Y ; bit1: write split H/L
// ---------------------------------------------------------------------------
template<int MODE>
__global__ void __launch_bounds__(256) ln_kernel(const float* __restrict__ X,
                                                 const float* __restrict__ gamma,
                                                 const float* __restrict__ beta,
                                                 float* __restrict__ Y,
                                                 __nv_bfloat16* __restrict__ H,
                                                 __nv_bfloat16* __restrict__ L)
{
    const int row = blockIdx.x;
    const int tid = threadIdx.x;
    const float4* x4 = reinterpret_cast<const float4*>(X + (size_t)row * DMODEL);
    float4 a = x4[tid];

    float s  = a.x + a.y + a.z + a.w;
    float ss = a.x*a.x + a.y*a.y + a.z*a.z + a.w*a.w;

    #pragma unroll
    for (int off = 16; off > 0; off >>= 1) {
        s  += __shfl_xor_sync(0xffffffff, s,  off);
        ss += __shfl_xor_sync(0xffffffff, ss, off);
    }
    __shared__ float red_s[8], red_ss[8];
    __shared__ float s_mu, s_inv;
    int wid = tid >> 5, lane = tid & 31;
    if (lane == 0) { red_s[wid] = s; red_ss[wid] = ss; }
    __syncthreads();
    if (tid == 0) {
        float ts = 0.f, tss = 0.f;
        #pragma unroll
        for (int i = 0; i < 8; i++) { ts += red_s[i]; tss += red_ss[i]; }
        float mu  = ts * (1.0f / DMODEL);
        float var = tss * (1.0f / DMODEL) - mu * mu;
        s_mu  = mu;
        s_inv = rsqrtf(var + LN_EPS);
    }
    __syncthreads();
    float mu = s_mu, inv = s_inv;

    float4 g4 = reinterpret_cast<const float4*>(gamma)[tid];
    float4 b4 = reinterpret_cast<const float4*>(beta)[tid];
    float4 o;
    o.x = (a.x - mu) * inv * g4.x + b4.x;
    o.y = (a.y - mu) * inv * g4.y + b4.y;
    o.z = (a.z - mu) * inv * g4.z + b4.z;
    o.w = (a.w - mu) * inv * g4.w + b4.w;
    if (MODE & 1)
        reinterpret_cast<float4*>(Y + (size_t)row * DMODEL)[tid] = o;
    if (MODE & 2) {
        const size_t base = (size_t)row * DMODEL + tid * 4;
        uint32_t h01, l01, h23, l23;
        pack_split2(o.x, o.y, h01, l01);
        pack_split2(o.z, o.w, h23, l23);
        uint2 hv = make_uint2(h01, h23), lv = make_uint2(l01, l23);
        *reinterpret_cast<uint2*>(H + base) = hv;
        *reinterpret_cast<uint2*>(L + base) = lv;
    }
}

// ---------------------------------------------------------------------------
// Activation split: fp32 -> bf16 hi/lo (only used for raw input x)
// ---------------------------------------------------------------------------
__global__ void __launch_bounds__(256) split_act(const float* __restrict__ X,
                                                 __nv_bfloat16* __restrict__ H,
                                                 __nv_bfloat16* __restrict__ L)
{
    const int i = (blockIdx.x * 256 + threadIdx.x) * 4;
    float4 v = *reinterpret_cast<const float4*>(X + i);
    uint32_t h01, l01, h23, l23;
    pack_split2(v.x, v.y, h01, l01);
    pack_split2(v.z, v.w, h23, l23);
    uint2 hv = make_uint2(h01, h23), lv = make_uint2(l01, l23);
    *reinterpret_cast<uint2*>(H + i) = hv;
    *reinterpret_cast<uint2*>(L + i) = lv;
}

// ---------------------------------------------------------------------------
// Transpose + split: W[K,N] fp32 row-major -> Whi/Wlo[N,K] bf16 row-major
// ---------------------------------------------------------------------------
__global__ void __launch_bounds__(256) tsplit_kernel(const float* __restrict__ W,
                                                     __nv_bfloat16* __restrict__ Bh,
                                                     __nv_bfloat16* __restrict__ Bl)
{
    __shared__ float t[32][33];
    const int n0 = blockIdx.x * 32, k0 = blockIdx.y * 32;
    const int tx = threadIdx.x, ty = threadIdx.y;
    #pragma unroll
    for (int r = 0; r < 4; r++)
        t[ty + 8*r][tx] = W[(size_t)(k0 + ty + 8*r) * DMODEL + n0 + tx];
    __syncthreads();
    #pragma unroll
    for (int r = 0; r < 4; r++) {
        int n = n0 + ty + 8*r;
        float a = t[tx][ty + 8*r];
        __nv_bfloat16 hi, lo;
        bf16_split(a, hi, lo);
        Bh[(size_t)n * DMODEL + k0 + tx] = hi;
        Bl[(size_t)n * DMODEL + k0 + tx] = lo;
    }
}

// ---------------------------------------------------------------------------
// Tensor-core split-bf16 GEMM: 512 threads, CTA tile 128x256, K-chunk 32,
// 2-stage cp.async pipeline, ldmatrix fragments, warp tile 64x32 (2x8 warps).
// EPI 0: bias -> split bf16 out. EPI 1: bias+relu -> split bf16 out.
// EPI 2: bias+residual -> fp32 out.
// ---------------------------------------------------------------------------
#define GP 40
#define S_AHI 0
#define S_ALO (128 * GP)
#define S_BHI (2 * 128 * GP)
#define S_BLO (2 * 128 * GP + 256 * GP)
#define STAGE_ELEMS ((2 * 128 + 2 * 256) * GP)   // 30720 bf16
#define GEMM_SMEM_BYTES (2 * STAGE_ELEMS * 2)    // 122880 B
#define NCH (DMODEL / 32)                        // 32 chunks

template<int EPI>
__global__ void __launch_bounds__(512, 1) mma_gemm(const __nv_bfloat16* __restrict__ Ah,
                                                   const __nv_bfloat16* __restrict__ Al,
                                                   const __nv_bfloat16* __restrict__ Wh,
                                                   const __nv_bfloat16* __restrict__ Wl,
                                                   const float* __restrict__ bias,
                                                   const float* __restrict__ resid,
                                                   float* __restrict__ C,
                                                   __nv_bfloat16* __restrict__ Ch,
                                                   __nv_bfloat16* __restrict__ Cl)
{
    extern __shared__ __nv_bfloat16 sm[];
    const uint32_t smb = smem_to_u32(sm);
    const int tid  = threadIdx.x;
    const int wid  = tid >> 5;
    const int lane = tid & 31;
    const int gid  = lane >> 2;
    const int tig  = lane & 3;
    const int g8   = lane >> 3;     // 0..3
    const int r8   = lane & 7;
    const int brow = blockIdx.y * 128;
    const int bcol = blockIdx.x * 256;
    const int m0   = (wid >> 3) * 64;     // 0,64
    const int n0   = (wid & 7) * 32;      // 0..224

    const __nv_bfloat16* gA[2] = { Ah + (size_t)brow * DMODEL,
                                   Al + (size_t)brow * DMODEL };
    const __nv_bfloat16* gW[2] = { Wh + (size_t)bcol * DMODEL,
                                   Wl + (size_t)bcol * DMODEL };

    // fill one 32-wide chunk: A 2x128x4 units + W 2x256x4 units = 3072 / 512 thr
    auto issue = [&](int chunk, int stage) {
        const int k0 = chunk * 32;
        const uint32_t sbase = smb + (uint32_t)(stage * STAGE_ELEMS) * 2;
        #pragma unroll
        for (int j = 0; j < 2; j++) {        // A hi/lo
            const int r = tid >> 2;
            const int c = (tid & 3) * 8;
            cp16(sbase + (uint32_t)((j ? S_ALO : S_AHI) + r * GP + c) * 2,
                 gA[j] + (size_t)r * DMODEL + k0 + c);
        }
        #pragma unroll
        for (int j = 0; j < 4; j++) {        // W hi/lo, 2 passes each
            const int arr = j >> 1;
            const int rem = ((j & 1) << 9) + tid;    // 0..1023
            const int r   = rem >> 2;                // 0..255
            const int c   = (rem & 3) * 8;
            cp16(sbase + (uint32_t)((arr ? S_BLO : S_BHI) + r * GP + c) * 2,
                 gW[arr] + (size_t)r * DMODEL + k0 + c);
        }
        CP_COMMIT();
    };

    float acc[4][4][4] = {};

    issue(0, 0);
    for (int i = 0; i < NCH; i++) {
        CP_WAIT0();
        __syncthreads();
        if (i + 1 < NCH) issue(i + 1, (i + 1) & 1);

        const uint32_t sb = smb + (uint32_t)((i & 1) * STAGE_ELEMS) * 2;
        #pragma unroll
        for (int s = 0; s < 2; s++) {
            const int kb = s * 16;
            uint32_t ah[4][4], al[4][4];
            #pragma unroll
            for (int mf = 0; mf < 4; mf++) {
                const int row = m0 + mf*16 + ((g8 & 1) << 3) + r8;
                const int col = kb + ((g8 >> 1) << 3);
                ldmx4(ah[mf], sb + (uint32_t)(S_AHI + row*GP + col) * 2);
                ldmx4(al[mf], sb + (uint32_t)(S_ALO + row*GP + col) * 2);
            }
            #pragma unroll
            for (int nf = 0; nf < 4; nf++) {
                const int rowB = n0 + nf*8 + r8;
                const int colB = kb + ((g8 & 1) << 3);
                uint32_t bh[2], bl[2];
                ldmx2(bh, sb + (uint32_t)(S_BHI + rowB*GP + colB) * 2);
                ldmx2(bl, sb + (uint32_t)(S_BLO + rowB*GP + colB) * 2);
                #pragma unroll
                for (int mf = 0; mf < 4; mf++) {
                    mma16816(acc[mf][nf], ah[mf], bh);
                    mma16816(acc[mf][nf], ah[mf], bl);
                    mma16816(acc[mf][nf], al[mf], bh);
                }
            }
        }
        __syncthreads();
    }

    // ---- epilogue ----
    #pragma unroll
    for (int mf = 0; mf < 4; mf++) {
        #pragma unroll
        for (int nf = 0; nf < 4; nf++) {
            const int row0 = brow + m0 + mf*16 + gid;
            const int col  = bcol + n0 + nf*8 + tig*2;
            float2 bv = *reinterpret_cast<const float2*>(&bias[col]);
            float o0 = acc[mf][nf][0] + bv.x;
            float o1 = acc[mf][nf][1] + bv.y;
            float o2 = acc[mf][nf][2] + bv.x;
            float o3 = acc[mf][nf][3] + bv.y;
            if (EPI == 1) {
                o0 = fmaxf(o0, 0.f); o1 = fmaxf(o1, 0.f);
                o2 = fmaxf(o2, 0.f); o3 = fmaxf(o3, 0.f);
            }
            if (EPI == 2) {
                float2 r0 = *reinterpret_cast<const float2*>(&resid[(size_t)row0 * DMODEL + col]);
                float2 r1 = *reinterpret_cast<const float2*>(&resid[(size_t)(row0+8) * DMODEL + col]);
                o0 += r0.x; o1 += r0.y; o2 += r1.x; o3 += r1.y;
                *reinterpret_cast<float2*>(&C[(size_t)row0 * DMODEL + col])     = make_float2(o0, o1);
                *reinterpret_cast<float2*>(&C[(size_t)(row0+8) * DMODEL + col]) = make_float2(o2, o3);
            } else {
                uint32_t h01, l01, h23, l23;
                pack_split2(o0, o1, h01, l01);
                pack_split2(o2, o3, h23, l23);
                *reinterpret_cast<uint32_t*>(&Ch[(size_t)row0 * DMODEL + col])     = h01;
                *reinterpret_cast<uint32_t*>(&Cl[(size_t)row0 * DMODEL + col])     = l01;
                *reinterpret_cast<uint32_t*>(&Ch[(size_t)(row0+8) * DMODEL + col]) = h23;
                *reinterpret_cast<uint32_t*>(&Cl[(size_t)(row0+8) * DMODEL + col]) = l23;
            }
        }
    }
}

// ---------------------------------------------------------------------------
// Tensor-core flash attention (pre-split Q/K/V, cp.async, ldmatrix, trans-V).
// Output: concat written pre-split to Oh/Ol.
// ---------------------------------------------------------------------------
#define ATS 72
#define AQ_HI 0
#define AQ_LO (128 * ATS)
#define AKV_BASE (2 * 128 * ATS)
#define KV_STAGE (4 * 64 * ATS)
#define KV_KHI 0
#define KV_KLO (64 * ATS)
#define KV_VHI (2 * 64 * ATS)
#define KV_VLO (3 * 64 * ATS)
#define ATTN_SMEM_BYTES ((AKV_BASE + 2 * KV_STAGE) * 2)   // 110592 B
#define NKT (SEQ / 64)   // 16 key tiles

__global__ void __launch_bounds__(256) attn_mma_kernel(
    const __nv_bfloat16* __restrict__ Qh, const __nv_bfloat16* __restrict__ Ql,
    const __nv_bfloat16* __restrict__ Kh, const __nv_bfloat16* __restrict__ Kl,
    const __nv_bfloat16* __restrict__ Vh, const __nv_bfloat16* __restrict__ Vl,
    const float* __restrict__ mask,
    const unsigned char* __restrict__ kpm,
    __nv_bfloat16* __restrict__ Oh, __nv_bfloat16* __restrict__ Ol)
{
    extern __shared__ __nv_bfloat16 sma[];
    const uint32_t smb = smem_to_u32(sma);
    const int tid  = threadIdx.x;
    const int wid  = tid >> 5;
    const int lane = tid & 31;
    const int gid  = lane >> 2;
    const int tig  = lane & 3;
    const int g8   = lane >> 3;
    const int r8   = lane & 7;
    const int bh   = blockIdx.y;
    const int b    = bh / NHEADS;
    const int h    = bh % NHEADS;
    const int q0   = blockIdx.x * 128;
    const int qw0  = wid * 16;
    const float scale = 0.125f;

    const __nv_bfloat16* qsrc[2] = {
        Qh + (size_t)(b*SEQ + q0) * DMODEL + h*DK,
        Ql + (size_t)(b*SEQ + q0) * DMODEL + h*DK };
    const __nv_bfloat16* kvsrc[4] = {
        Kh + (size_t)(b*SEQ) * DMODEL + h*DK,
        Kl + (size_t)(b*SEQ) * DMODEL + h*DK,
        Vh + (size_t)(b*SEQ) * DMODEL + h*DK,
        Vl + (size_t)(b*SEQ) * DMODEL + h*DK };

    {
        #pragma unroll
        for (int j = 0; j < 8; j++) {
            const int arr = j >> 2;
            const int rem = ((j & 3) << 8) + tid;
            const int r   = rem >> 3;
            const int c   = (rem & 7) * 8;
            const uint32_t dst = smb +
                (uint32_t)((arr ? AQ_LO : AQ_HI) + r*ATS + c) * 2;
            cp16(dst, qsrc[arr] + (size_t)r * DMODEL + c);
        }
    }
    auto issue_kv = [&](int kt, int stage) {
        #pragma unroll
        for (int j = 0; j < 8; j++) {
            const int arr = j >> 1;
            const int rem = ((j & 1) << 8) + tid;
            const int r   = rem >> 3;
            const int c   = (rem & 7) * 8;
            const uint32_t dst = smb +
                (uint32_t)(AKV_BASE + stage*KV_STAGE + arr*(64*ATS) + r*ATS + c) * 2;
            cp16(dst, kvsrc[arr] + (size_t)(kt*64 + r) * DMODEL + c);
        }
        CP_COMMIT();
    };
    issue_kv(0, 0);

    float ctx[8][4] = {};
    float mrow0 = -1e30f, mrow1 = -1e30f;
    float lrow0 = 0.f,    lrow1 = 0.f;

    const int r0g = q0 + qw0 + gid;
    const int r1g = r0g + 8;

    for (int i = 0; i < NKT; i++) {
        CP_WAIT0();
        __syncthreads();
        if (i + 1 < NKT) issue_kv(i + 1, (i + 1) & 1);

        const uint32_t kvb = smb + (uint32_t)(AKV_BASE + (i & 1)*KV_STAGE) * 2;
        const int kt = i * 64;

        float sacc[8][4] = {};
        #pragma unroll
        for (int ks = 0; ks < 4; ks++) {
            const int kb = ks * 16;
            uint32_t qh[4], ql[4];
            {
                const int row = qw0 + ((g8 & 1) << 3) + r8;
                const int col = kb + ((g8 >> 1) << 3);
                ldmx4(qh, smb + (uint32_t)(AQ_HI + row*ATS + col) * 2);
                ldmx4(ql, smb + (uint32_t)(AQ_LO + row*ATS + col) * 2);
            }
            #pragma unroll
            for (int nt = 0; nt < 8; nt++) {
                const int rowB = nt*8 + r8;
                const int colB = kb + ((g8 & 1) << 3);
                uint32_t kh[2], kl[2];
                ldmx2(kh, kvb + (uint32_t)(KV_KHI + rowB*ATS + colB) * 2);
                ldmx2(kl, kvb + (uint32_t)(KV_KLO + rowB*ATS + colB) * 2);
                mma16816(sacc[nt], qh, kh);
                mma16816(sacc[nt], qh, kl);
                mma16816(sacc[nt], ql, kh);
            }
        }

        float mt0 = -1e30f, mt1 = -1e30f;
        #pragma unroll
        for (int nt = 0; nt < 8; nt++) {
            const int c = kt + nt*8 + tig*2;
            const float ka0 = kpm[b*SEQ + c]     ? -1e30f : 0.f;
            const float ka1 = kpm[b*SEQ + c + 1] ? -1e30f : 0.f;
            float2 m0 = *reinterpret_cast<const float2*>(&mask[(size_t)r0g * SEQ + c]);
            float2 m1 = *reinterpret_cast<const float2*>(&mask[(size_t)r1g * SEQ + c]);
            sacc[nt][0] = sacc[nt][0]*scale + m0.x + ka0;
            sacc[nt][1] = sacc[nt][1]*scale + m0.y + ka1;
            sacc[nt][2] = sacc[nt][2]*scale + m1.x + ka0;
            sacc[nt][3] = sacc[nt][3]*scale + m1.y + ka1;
            mt0 = fmaxf(mt0, fmaxf(sacc[nt][0], sacc[nt][1]));
            mt1 = fmaxf(mt1, fmaxf(sacc[nt][2], sacc[nt][3]));
        }
        mt0 = fmaxf(mt0, __shfl_xor_sync(0xffffffff, mt0, 1));
        mt0 = fmaxf(mt0, __shfl_xor_sync(0xffffffff, mt0, 2));
        mt1 = fmaxf(mt1, __shfl_xor_sync(0xffffffff, mt1, 1));
        mt1 = fmaxf(mt1, __shfl_xor_sync(0xffffffff, mt1, 2));

        const float mn0 = fmaxf(mrow0, mt0);
        const float mn1 = fmaxf(mrow1, mt1);
        const float corr0 = __expf(mrow0 - mn0);
        const float corr1 = __expf(mrow1 - mn1);
        mrow0 = mn0; mrow1 = mn1;

        float ps0 = 0.f, ps1 = 0.f;
        #pragma unroll
        for (int nt = 0; nt < 8; nt++) {
            sacc[nt][0] = __expf(sacc[nt][0] - mn0);
            sacc[nt][1] = __expf(sacc[nt][1] - mn0);
            sacc[nt][2] = __expf(sacc[nt][2] - mn1);
            sacc[nt][3] = __expf(sacc[nt][3] - mn1);
            ps0 += sacc[nt][0] + sacc[nt][1];
            ps1 += sacc[nt][2] + sacc[nt][3];
        }
        ps0 += __shfl_xor_sync(0xffffffff, ps0, 1);
        ps0 += __shfl_xor_sync(0xffffffff, ps0, 2);
        ps1 += __shfl_xor_sync(0xffffffff, ps1, 1);
        ps1 += __shfl_xor_sync(0xffffffff, ps1, 2);
        lrow0 = lrow0 * corr0 + ps0;
        lrow1 = lrow1 * corr1 + ps1;

        #pragma unroll
        for (int dt = 0; dt < 8; dt++) {
            ctx[dt][0] *= corr0; ctx[dt][1] *= corr0;
            ctx[dt][2] *= corr1; ctx[dt][3] *= corr1;
        }

        #pragma unroll
        for (int ks = 0; ks < 4; ks++) {
            uint32_t ph[4], pl[4];
            pack_split2(sacc[2*ks][0],   sacc[2*ks][1],   ph[0], pl[0]);
            pack_split2(sacc[2*ks][2],   sacc[2*ks][3],   ph[1], pl[1]);
            pack_split2(sacc[2*ks+1][0], sacc[2*ks+1][1], ph[2], pl[2]);
            pack_split2(sacc[2*ks+1][2], sacc[2*ks+1][3], ph[3], pl[3]);
            const int rowV = ks*16 + ((g8 & 1) << 3) + r8;
            #pragma unroll
            for (int dt = 0; dt < 8; dt++) {
                uint32_t vh[2], vl[2];
                ldmx2t(vh, kvb + (uint32_t)(KV_VHI + rowV*ATS + dt*8) * 2);
                ldmx2t(vl, kvb + (uint32_t)(KV_VLO + rowV*ATS + dt*8) * 2);
                mma16816(ctx[dt], ph, vh);
                mma16816(ctx[dt], ph, vl);
                mma16816(ctx[dt], pl, vh);
            }
        }
        __syncthreads();
    }

    const float inv0 = 1.f / lrow0;
    const float inv1 = 1.f / lrow1;
    #pragma unroll
    for (int dt = 0; dt < 8; dt++) {
        const int col = h*DK + dt*8 + tig*2;
        uint32_t h01, l01, h23, l23;
        pack_split2(ctx[dt][0]*inv0, ctx[dt][1]*inv0, h01, l01);
        pack_split2(ctx[dt][2]*inv1, ctx[dt][3]*inv1, h23, l23);
        *reinterpret_cast<uint32_t*>(&Oh[(size_t)(b*SEQ + r0g) * DMODEL + col]) = h01;
        *reinterpret_cast<uint32_t*>(&Ol[(size_t)(b*SEQ + r0g) * DMODEL + col]) = l01;
        *reinterpret_cast<uint32_t*>(&Oh[(size_t)(b*SEQ + r1g) * DMODEL + col]) = h23;
        *reinterpret_cast<uint32_t*>(&Ol[(size_t)(b*SEQ + r1g) * DMODEL + col]) = l23;
    }
}

// ---------------------------------------------------------------------------
// Launch
// ---------------------------------------------------------------------------
extern "C" void kernel_launch(void* const* d_in, const int* in_sizes, int n_in,
                              void* d_out, int out_size)
{
    const float* x    = (const float*)d_in[0];
    const float* mask = (const float*)d_in[1];
    const unsigned char* kpm = (const unsigned char*)d_in[2];
    const float* g1   = (const float*)d_in[3];
    const float* b1n  = (const float*)d_in[4];
    const float* Wq   = (const float*)d_in[5];
    const float* bq   = (const float*)d_in[6];
    const float* Wk   = (const float*)d_in[7];
    const float* bk   = (const float*)d_in[8];
    const float* Wv   = (const float*)d_in[9];
    const float* bv   = (const float*)d_in[10];
    const float* Wo   = (const float*)d_in[11];
    const float* bo   = (const float*)d_in[12];
    const float* W1   = (const float*)d_in[13];
    const float* b1   = (const float*)d_in[14];
    const float* W2   = (const float*)d_in[15];
    const float* b2   = (const float*)d_in[16];
    float* out = (float*)d_out;

    float *B2, *B3;
    __nv_bfloat16 *WHI, *WLO, *AHI, *ALO, *QHI, *QLO, *KHI, *KLO, *VHI, *VLO;
    cudaGetSymbolAddress((void**)&B2, g_buf2);
    cudaGetSymbolAddress((void**)&B3, g_buf3);
    cudaGetSymbolAddress((void**)&WHI, g_whi);
    cudaGetSymbolAddress((void**)&WLO, g_wlo);
    cudaGetSymbolAddress((void**)&AHI, g_ahi);
    cudaGetSymbolAddress((void**)&ALO, g_alo);
    cudaGetSymbolAddress((void**)&QHI, g_qhi);
    cudaGetSymbolAddress((void**)&QLO, g_qlo);
    cudaGetSymbolAddress((void**)&KHI, g_khi);
    cudaGetSymbolAddress((void**)&KLO, g_klo);
    cudaGetSymbolAddress((void**)&VHI, g_vhi);
    cudaGetSymbolAddress((void**)&VLO, g_vlo);

    cudaFuncSetAttribute(mma_gemm<0>, cudaFuncAttributeMaxDynamicSharedMemorySize, GEMM_SMEM_BYTES);
    cudaFuncSetAttribute(mma_gemm<1>, cudaFuncAttributeMaxDynamicSharedMemorySize, GEMM_SMEM_BYTES);
    cudaFuncSetAttribute(mma_gemm<2>, cudaFuncAttributeMaxDynamicSharedMemorySize, GEMM_SMEM_BYTES);
    cudaFuncSetAttribute(attn_mma_kernel, cudaFuncAttributeMaxDynamicSharedMemorySize, ATTN_SMEM_BYTES);

    const int M = MROWS;
    dim3 gGrid(DMODEL / 256, M / 128);          // (4, 32) = 128 CTAs
    dim3 tGrid(DMODEL / 32, DMODEL / 32);       // (32, 32)
    dim3 tBlk(32, 8);
    dim3 aGrid(SEQ / 128, BATCH * NHEADS);      // (8, 64)
    const int sGrid = (MROWS * DMODEL) / (256 * 4);   // 4096

    // 1. LN1(x) -> split only (AHI/ALO)
    ln_kernel<2><<<M, 256>>>(x, g1, b1n, nullptr, AHI, ALO);
    // 2. q = LN1(x)@Wq+bq -> split (QHI/QLO)
    tsplit_kernel<<<tGrid, tBlk>>>(Wq, WHI, WLO);
    mma_gemm<0><<<gGrid, 512, GEMM_SMEM_BYTES>>>(AHI, ALO, WHI, WLO, bq, nullptr,
                                                 nullptr, QHI, QLO);
    // 3. x split -> AHI/ALO (shared by k and v GEMMs)
    split_act<<<sGrid, 256>>>(x, AHI, ALO);
    tsplit_kernel<<<tGrid, tBlk>>>(Wk, WHI, WLO);
    mma_gemm<0><<<gGrid, 512, GEMM_SMEM_BYTES>>>(AHI, ALO, WHI, WLO, bk, nullptr,
                                                 nullptr, KHI, KLO);
    tsplit_kernel<<<tGrid, tBlk>>>(Wv, WHI, WLO);
    mma_gemm<0><<<gGrid, 512, GEMM_SMEM_BYTES>>>(AHI, ALO, WHI, WLO, bv, nullptr,
                                                 nullptr, VHI, VLO);
    // 4. attention -> split concat (AHI/ALO)
    attn_mma_kernel<<<aGrid, 256, ATTN_SMEM_BYTES>>>(QHI, QLO, KHI, KLO, VHI, VLO,
                                                     mask, kpm, AHI, ALO);
    // 5. x2 = concat@Wo + bo + x  (fp32, B2)
    tsplit_kernel<<<tGrid, tBlk>>>(Wo, WHI, WLO);
    mma_gemm<2><<<gGrid, 512, GEMM_SMEM_BYTES>>>(AHI, ALO, WHI, WLO, bo, x,
                                                 B2, nullptr, nullptr);
    // 6. LN2(x2) -> fp32 (B3, residual) + split (AHI/ALO)
    ln_kernel<3><<<M, 256>>>(B2, g1, b1n, B3, AHI, ALO);
    // 7. h = relu(LN2@W1+b1) -> split (QHI/QLO)
    tsplit_kernel<<<tGrid, tBlk>>>(W1, WHI, WLO);
    mma_gemm<1><<<gGrid, 512, GEMM_SMEM_BYTES>>>(AHI, ALO, WHI, WLO, b1, nullptr,
                                                 nullptr, QHI, QLO);
    // 8. out = LN2 + h@W2 + b2
    tsplit_kernel<<<tGrid, tBlk>>>(W2, WHI, WLO);
    mma_gemm<2><<<gGrid, 512, GEMM_SMEM_BYTES>>>(QHI, QLO, WHI, WLO, b2, B3,
                                                 out, nullptr, nullptr);
}